// round 7
// baseline (speedup 1.0000x reference)
#include <cuda_runtime.h>
#include <cuda_bf16.h>
#include <cstddef>

// ---------------------------------------------------------------------------
// 2-layer TF LSTM: B=32, T=512, INSZ=HSZ=1024, G=4096.
// Output: concat(out1[32,512,1024], h1[32,1024], c1[32,1024]) f32.
// ---------------------------------------------------------------------------

#define BSZ   32
#define TSTEP 512
#define HS    1024
#define GSZ   4096
#define MROWS (BSZ * TSTEP)      // 16384
#define NBLK  128                // persistent CTAs for recurrence

typedef unsigned long long u64;

// ----------------------------- device scratch ------------------------------
__device__ __align__(16) float g_xproj[(size_t)MROWS * GSZ];  // 256 MB
__device__ __align__(16) float g_out0 [(size_t)MROWS * HS];   //  64 MB
__device__ __align__(16) float g_hbuf [2 * HS * BSZ];         // ping-pong h, [buf][k][b]
__device__ unsigned g_cnt[4];    // per-quarter producer counters

// ----------------------------- f32x2 helpers -------------------------------
__device__ __forceinline__ u64 pack2(float lo, float hi) {
    u64 r; asm("mov.b64 %0, {%1, %2};" : "=l"(r) : "f"(lo), "f"(hi)); return r;
}
__device__ __forceinline__ void unpack2(u64 v, float& lo, float& hi) {
    asm("mov.b64 {%0, %1}, %2;" : "=f"(lo), "=f"(hi) : "l"(v));
}
__device__ __forceinline__ u64 ffma2(u64 a, u64 b, u64 c) {
    u64 d; asm("fma.rn.f32x2 %0, %1, %2, %3;" : "=l"(d) : "l"(a), "l"(b), "l"(c)); return d;
}
__device__ __forceinline__ u64 add2(u64 a, u64 b) {
    u64 d; asm("add.rn.f32x2 %0, %1, %2;" : "=l"(d) : "l"(a), "l"(b)); return d;
}
__device__ __forceinline__ float sigf(float x) { return 1.0f / (1.0f + __expf(-x)); }

// ----------------------------- counter reset -------------------------------
__global__ void init_cnt_kernel() {
    if (threadIdx.x < 4) g_cnt[threadIdx.x] = 0u;
}

// ---------------------------------------------------------------------------
// GEMM (R2 config, measured fma=66.5%): C = A[.,0:1024] @ W[0:1024,.] + bias
// Tile 128(m) x 64(n), BK=16, 256 threads, microtile 8x4 with f32x2 pairs.
// ---------------------------------------------------------------------------
#define GBM 128
#define GBN 64
#define GBK 16

__global__ void __launch_bounds__(256) gemm_kernel(
    const float* __restrict__ A, const float* __restrict__ W,
    const float* __restrict__ bias, float* __restrict__ C)
{
    __shared__ float Ash[GBK][132];
    __shared__ __align__(16) float Bsh[GBK][GBN];

    const int tid = threadIdx.x;
    const int m0  = blockIdx.y * GBM;
    const int n0  = blockIdx.x * GBN;
    const int tm  = tid >> 4;
    const int tn  = tid & 15;

    u64 acc[8][2];
    {
        float4 bv = *(const float4*)(bias + n0 + tn * 4);
        u64 b01 = pack2(bv.x, bv.y), b23 = pack2(bv.z, bv.w);
#pragma unroll
        for (int i = 0; i < 8; i++) { acc[i][0] = b01; acc[i][1] = b23; }
    }

    for (int k0 = 0; k0 < HS; k0 += GBK) {
#pragma unroll
        for (int r = 0; r < 2; r++) {
            int f = tid + r * 256;
            int m = f >> 2, kq = (f & 3) * 4;
            float4 av = *(const float4*)(A + (size_t)(m0 + m) * HS + k0 + kq);
            Ash[kq + 0][m] = av.x; Ash[kq + 1][m] = av.y;
            Ash[kq + 2][m] = av.z; Ash[kq + 3][m] = av.w;
        }
        {
            int k = tid >> 4, n4 = (tid & 15) * 4;
            *(float4*)&Bsh[k][n4] =
                *(const float4*)(W + (size_t)(k0 + k) * GSZ + n0 + n4);
        }
        __syncthreads();

#pragma unroll
        for (int kk = 0; kk < GBK; kk++) {
            float4 a0 = *(const float4*)&Ash[kk][tm * 8];
            float4 a1 = *(const float4*)&Ash[kk][tm * 8 + 4];
            float4 b4 = *(const float4*)&Bsh[kk][tn * 4];
            u64 w01 = pack2(b4.x, b4.y), w23 = pack2(b4.z, b4.w);
            float am[8] = {a0.x, a0.y, a0.z, a0.w, a1.x, a1.y, a1.z, a1.w};
#pragma unroll
            for (int i = 0; i < 8; i++) {
                u64 ai = pack2(am[i], am[i]);
                acc[i][0] = ffma2(ai, w01, acc[i][0]);
                acc[i][1] = ffma2(ai, w23, acc[i][1]);
            }
        }
        __syncthreads();
    }

#pragma unroll
    for (int i = 0; i < 8; i++) {
        float x0, x1, x2, x3;
        unpack2(acc[i][0], x0, x1);
        unpack2(acc[i][1], x2, x3);
        *(float4*)(C + (size_t)(m0 + tm * 8 + i) * GSZ + n0 + tn * 4) =
            make_float4(x0, x1, x2, x3);
    }
}

// ---------------------------------------------------------------------------
// Recurrence: persistent, 128 CTAs x 256 threads (8 warps).
// CTA c owns hidden cols 8c..8c+7 (all in K-quarter c>>5) -> 32 gate cols.
// Warp w: gate pair p=w&1 (16 cols), k-subchunk k64=w>>1 within the quarter.
// Dataflow sync: per-quarter counters replace the full grid barrier. h(t)
// quarter g is readable once g_cnt[g] >= 32*(t+1) (release-arrive by its 32
// producer CTAs at end of step t-1; acquire-wait by consumers right before
// staging quarter g). End of step is arrive-only: no global spin.
// ---------------------------------------------------------------------------
// smem floats: Wsh 32768 | hsh 2*8192 | zsh 4096 | csh 256 | hown 256 | len 32
#define REC_SMEM_FLOATS (32768 + 16384 + 4096 + 256 + 256 + 32)
#define REC_SMEM_BYTES  (REC_SMEM_FLOATS * 4)

__device__ __forceinline__ void wait_cnt(const unsigned* p, unsigned target)
{
    unsigned v;
    do {
        asm volatile("ld.acquire.gpu.global.u32 %0, [%1];"
                     : "=r"(v) : "l"(p) : "memory");
    } while (v < target);
}

__device__ __forceinline__ void arrive_cnt(unsigned* p)
{
    asm volatile("red.release.gpu.global.add.u32 [%0], %1;"
                 :: "l"(p), "r"(1u) : "memory");
}

__global__ void __launch_bounds__(256) rec_kernel(
    const float* __restrict__ xproj,   // [16384,4096] (bias already added)
    const float* __restrict__ W,       // [2048,4096]; rows 1024.. are Wh
    const int*   __restrict__ lengths, // [32]
    float*       __restrict__ out_h,   // [32,512,1024]
    float*       __restrict__ hc_final)// null, or [h1 | c1]
{
    extern __shared__ __align__(16) float sm[];
    float* Wsh   = sm;                   // [k][j], j = g*8+jh, 1024*32
    float* hsh   = Wsh + 32768;          // 2 buffers x [kk<256][b]
    float* zsh   = hsh + 16384;          // [g][k64][b*8+jh], 4*4*256
    float* csh   = zsh + 4096;
    float* hown  = csh + 256;
    int*   lensh = (int*)(hown + 256);

    const int tid = threadIdx.x;
    const int blk = blockIdx.x;
    const int b   = tid & 31;
    const int w   = tid >> 5;            // 0..7
    const int p   = w & 1;               // gate pair: gates 2p, 2p+1
    const int k64 = w >> 1;              // k-subchunk within quarter, 0..3
    const int myq = blk >> 5;            // K-quarter this CTA produces

    for (int i = tid; i < 32768; i += 256) {
        int k = i >> 5, j = i & 31;
        int qq = j >> 3, jh = j & 7;
        Wsh[i] = W[(size_t)(HS + k) * GSZ + qq * HS + blk * 8 + jh];
    }
    if (tid < 32) lensh[tid] = lengths[tid];
    csh[tid] = 0.0f; hown[tid] = 0.0f;
    __stcg(&g_hbuf[blk * 256 + tid], 0.0f);   // publish h(0) = 0 slice

    __syncthreads();
    if (tid == 0) arrive_cnt(&g_cnt[myq]);    // h(0) quarter arrival

    int cur = 0;
    const ulonglong2* Wsh2 = (const ulonglong2*)Wsh;

    for (int t = 0; t < TSTEP; t++) {
        const unsigned need = 32u * (unsigned)(t + 1);
        const float4* hq = (const float4*)(g_hbuf + (size_t)cur * 32768);
        float4* hsh4 = (float4*)hsh;

        // hoisted xproj loads (consumed ~5us later)
        ulonglong2 xv0, xv1, xv2, xv3;
        if (k64 == 0) {
            const float* xp = xproj + ((size_t)(b * TSTEP + t)) * GSZ + blk * 8;
            xv0 = *(const ulonglong2*)(xp + (2 * p)     * HS);
            xv1 = *(const ulonglong2*)(xp + (2 * p)     * HS + 4);
            xv2 = *(const ulonglong2*)(xp + (2 * p + 1) * HS);
            xv3 = *(const ulonglong2*)(xp + (2 * p + 1) * HS + 4);
        }

        // wait for quarter 0 producers, then stage quarter 0 into buffer 0
        if (tid == 0) wait_cnt(&g_cnt[0], need);
        __syncthreads();
#pragma unroll
        for (int r = 0; r < 8; r++)
            hsh4[tid + r * 256] = __ldcg(hq + tid + r * 256);
        __syncthreads();

        u64 acc[8];
#pragma unroll
        for (int i = 0; i < 8; i++) acc[i] = 0ull;

#pragma unroll
        for (int q = 0; q < 4; q++) {
            const int buf = q & 1;

            // wait for quarter q+1 (normally already satisfied), prefetch it
            float4 stg[8];
            if (q < 3) {
                if (tid == 0) wait_cnt(&g_cnt[q + 1], need);
                __syncthreads();
#pragma unroll
                for (int r = 0; r < 8; r++)
                    stg[r] = __ldcg(hq + (q + 1) * 2048 + tid + r * 256);
            }

            // compute on quarter q: this warp's 64-k subchunk, 16 gate cols
            const float* hb = hsh + buf * 8192 + k64 * 64 * 32 + b;
            const ulonglong2* Wr =
                Wsh2 + (size_t)(q * 256 + k64 * 64) * 8 + p * 4;
#pragma unroll 16
            for (int kk = 0; kk < 64; kk++) {
                float hv = hb[kk * 32];
                u64 h2 = pack2(hv, hv);
                ulonglong2 wA = Wr[kk * 8];
                ulonglong2 wB = Wr[kk * 8 + 1];
                ulonglong2 wC = Wr[kk * 8 + 2];
                ulonglong2 wD = Wr[kk * 8 + 3];
                acc[0] = ffma2(h2, wA.x, acc[0]);
                acc[1] = ffma2(h2, wA.y, acc[1]);
                acc[2] = ffma2(h2, wB.x, acc[2]);
                acc[3] = ffma2(h2, wB.y, acc[3]);
                acc[4] = ffma2(h2, wC.x, acc[4]);
                acc[5] = ffma2(h2, wC.y, acc[5]);
                acc[6] = ffma2(h2, wD.x, acc[6]);
                acc[7] = ffma2(h2, wD.y, acc[7]);
            }

            if (q < 3) {
                float4* dstb = (float4*)(hsh + (buf ^ 1) * 8192);
#pragma unroll
                for (int r = 0; r < 8; r++)
                    dstb[tid + r * 256] = stg[r];
                __syncthreads();
            }
        }

        // fold x into k64==0 partials
        if (k64 == 0) {
            acc[0] = add2(acc[0], xv0.x); acc[1] = add2(acc[1], xv0.y);
            acc[2] = add2(acc[2], xv1.x); acc[3] = add2(acc[3], xv1.y);
            acc[4] = add2(acc[4], xv2.x); acc[5] = add2(acc[5], xv2.y);
            acc[6] = add2(acc[6], xv3.x); acc[7] = add2(acc[7], xv3.y);
        }

        // store partials: zsh[g][k64][b][jh]
        {
            u64* z64 = (u64*)zsh;
#pragma unroll
            for (int gi = 0; gi < 2; gi++) {
                int g = 2 * p + gi;
                u64* dstz = z64 + ((g * 1024 + k64 * 256 + b * 8) >> 1);
                dstz[0] = acc[gi * 4 + 0];
                dstz[1] = acc[gi * 4 + 1];
                dstz[2] = acc[gi * 4 + 2];
                dstz[3] = acc[gi * 4 + 3];
            }
        }
        __syncthreads();

        // cell update: 256 units, one per thread
        const int nxt = cur ^ 1;
        {
            int u  = tid;
            int bu = u >> 3, jh = u & 7;
            float zq[4];
#pragma unroll
            for (int g = 0; g < 4; g++) {
                zq[g] = zsh[g * 1024 + u] + zsh[g * 1024 + 256 + u]
                      + zsh[g * 1024 + 512 + u] + zsh[g * 1024 + 768 + u];
            }
            float cp = csh[u];
            float cn = sigf(zq[2] + 1.0f) * cp + sigf(zq[0]) * tanhf(zq[1]);
            float hn = sigf(zq[3]) * tanhf(cn);
            bool mask = (t < lensh[bu]);
            float hk = mask ? hn : hown[u];
            float ck = mask ? cn : cp;
            csh[u]  = ck;
            hown[u] = hk;
            int kg = blk * 8 + jh;
            out_h[((size_t)bu * TSTEP + t) * HS + kg] = mask ? hn : 0.0f;
            __stcg(&g_hbuf[(size_t)nxt * 32768 + kg * 32 + bu], hk);
            if (hc_final != nullptr && t == TSTEP - 1) {
                hc_final[(size_t)bu * HS + kg]         = hk;
                hc_final[32768 + (size_t)bu * HS + kg] = ck;
            }
        }

        // publish h(t+1) quarter: arrive-only, no global spin
        __syncthreads();
        if (tid == 0) arrive_cnt(&g_cnt[myq]);
        cur = nxt;
    }
}

// ---------------------------------------------------------------------------
extern "C" void kernel_launch(void* const* d_in, const int* in_sizes, int n_in,
                              void* d_out, int out_size)
{
    const float* x       = (const float*)d_in[0];
    const int*   lengths = (const int*)  d_in[1];
    const float* W0      = (const float*)d_in[2];
    const float* b0      = (const float*)d_in[3];
    const float* W1      = (const float*)d_in[4];
    const float* b1      = (const float*)d_in[5];
    float*       out     = (float*)d_out;

    (void)in_sizes; (void)n_in; (void)out_size;

    cudaFuncSetAttribute(rec_kernel,
                         cudaFuncAttributeMaxDynamicSharedMemorySize,
                         REC_SMEM_BYTES);

    float* xproj = nullptr;
    float* out0  = nullptr;
    cudaGetSymbolAddress((void**)&xproj, g_xproj);
    cudaGetSymbolAddress((void**)&out0,  g_out0);

    dim3 ggrid(GSZ / GBN, MROWS / GBM);  // (64, 128)

    // Layer 0
    gemm_kernel<<<ggrid, 256>>>(x, W0, b0, xproj);
    init_cnt_kernel<<<1, 32>>>();
    rec_kernel<<<NBLK, 256, REC_SMEM_BYTES>>>(xproj, W0, lengths, out0, nullptr);

    // Layer 1
    gemm_kernel<<<ggrid, 256>>>(out0, W1, b1, xproj);
    init_cnt_kernel<<<1, 32>>>();
    rec_kernel<<<NBLK, 256, REC_SMEM_BYTES>>>(xproj, W1, lengths,
                                              out, out + (size_t)MROWS * HS);
}

// round 8
// speedup vs baseline: 1.0409x; 1.0409x over previous
#include <cuda_runtime.h>
#include <cuda_bf16.h>
#include <cstddef>

// ---------------------------------------------------------------------------
// 2-layer TF LSTM: B=32, T=512, INSZ=HSZ=1024, G=4096.
// Output: concat(out1[32,512,1024], h1[32,1024], c1[32,1024]) f32.
// ---------------------------------------------------------------------------

#define BSZ   32
#define TSTEP 512
#define HS    1024
#define GSZ   4096
#define MROWS (BSZ * TSTEP)      // 16384
#define NBLK  128                // persistent CTAs for recurrence

typedef unsigned long long u64;

// ----------------------------- device scratch ------------------------------
__device__ __align__(16) float g_xproj[(size_t)MROWS * GSZ];  // 256 MB
__device__ __align__(16) float g_out0 [(size_t)MROWS * HS];   //  64 MB
__device__ __align__(16) float g_hbuf [2 * HS * BSZ];         // ping-pong h, [buf][k][b]
__device__ unsigned g_bar;

// ----------------------------- f32x2 helpers -------------------------------
__device__ __forceinline__ u64 pack2(float lo, float hi) {
    u64 r; asm("mov.b64 %0, {%1, %2};" : "=l"(r) : "f"(lo), "f"(hi)); return r;
}
__device__ __forceinline__ void unpack2(u64 v, float& lo, float& hi) {
    asm("mov.b64 {%0, %1}, %2;" : "=f"(lo), "=f"(hi) : "l"(v));
}
__device__ __forceinline__ u64 ffma2(u64 a, u64 b, u64 c) {
    u64 d; asm("fma.rn.f32x2 %0, %1, %2, %3;" : "=l"(d) : "l"(a), "l"(b), "l"(c)); return d;
}
__device__ __forceinline__ float sigf(float x) { return 1.0f / (1.0f + __expf(-x)); }

// ----------------------------- barrier reset -------------------------------
__global__ void init_bar_kernel() { g_bar = 0u; }

// ---------------------------------------------------------------------------
// GEMM (measured-stable, fma=66.6%): C = A[.,0:1024] @ W[0:1024,.] + bias
// Tile 128(m) x 64(n), BK=16, 256 threads, microtile 8x4 with f32x2 pairs.
// ---------------------------------------------------------------------------
#define GBM 128
#define GBN 64
#define GBK 16

__global__ void __launch_bounds__(256) gemm_kernel(
    const float* __restrict__ A, const float* __restrict__ W,
    const float* __restrict__ bias, float* __restrict__ C)
{
    __shared__ float Ash[GBK][132];
    __shared__ __align__(16) float Bsh[GBK][GBN];

    const int tid = threadIdx.x;
    const int m0  = blockIdx.y * GBM;
    const int n0  = blockIdx.x * GBN;
    const int tm  = tid >> 4;
    const int tn  = tid & 15;

    u64 acc[8][2];
    {
        float4 bv = *(const float4*)(bias + n0 + tn * 4);
        u64 b01 = pack2(bv.x, bv.y), b23 = pack2(bv.z, bv.w);
#pragma unroll
        for (int i = 0; i < 8; i++) { acc[i][0] = b01; acc[i][1] = b23; }
    }

    for (int k0 = 0; k0 < HS; k0 += GBK) {
#pragma unroll
        for (int r = 0; r < 2; r++) {
            int f = tid + r * 256;
            int m = f >> 2, kq = (f & 3) * 4;
            float4 av = *(const float4*)(A + (size_t)(m0 + m) * HS + k0 + kq);
            Ash[kq + 0][m] = av.x; Ash[kq + 1][m] = av.y;
            Ash[kq + 2][m] = av.z; Ash[kq + 3][m] = av.w;
        }
        {
            int k = tid >> 4, n4 = (tid & 15) * 4;
            *(float4*)&Bsh[k][n4] =
                *(const float4*)(W + (size_t)(k0 + k) * GSZ + n0 + n4);
        }
        __syncthreads();

#pragma unroll
        for (int kk = 0; kk < GBK; kk++) {
            float4 a0 = *(const float4*)&Ash[kk][tm * 8];
            float4 a1 = *(const float4*)&Ash[kk][tm * 8 + 4];
            float4 b4 = *(const float4*)&Bsh[kk][tn * 4];
            u64 w01 = pack2(b4.x, b4.y), w23 = pack2(b4.z, b4.w);
            float am[8] = {a0.x, a0.y, a0.z, a0.w, a1.x, a1.y, a1.z, a1.w};
#pragma unroll
            for (int i = 0; i < 8; i++) {
                u64 ai = pack2(am[i], am[i]);
                acc[i][0] = ffma2(ai, w01, acc[i][0]);
                acc[i][1] = ffma2(ai, w23, acc[i][1]);
            }
        }
        __syncthreads();
    }

#pragma unroll
    for (int i = 0; i < 8; i++) {
        float x0, x1, x2, x3;
        unpack2(acc[i][0], x0, x1);
        unpack2(acc[i][1], x2, x3);
        *(float4*)(C + (size_t)(m0 + tm * 8 + i) * GSZ + n0 + tn * 4) =
            make_float4(x0, x1, x2, x3);
    }
}

// ---------------------------------------------------------------------------
// Recurrence: persistent, 128 CTAs x 512 threads (16 warps, 4/SMSP).
// CTA owns 8 hidden cols -> 32 gate cols. Warp w covers ALL 32 gate cols for
// a 16-k slice per quarter (k = q*256 + w*16 .. +16); lane = batch.
// Inner loop per k: 1 LDS(h) + 1 mov + 8 broadcast LDS.128(W) + 16 FFMA2.
// Partials accumulate in regs across quarters; 16 warp-slices reduced + xproj
// folded in the cell phase. Single-buffer h staging with register prefetch.
// ---------------------------------------------------------------------------
// smem floats: Wsh 32768 | hsh 8192 | zsh 16384 | csh 256 | hown 256 | len 32
#define REC_SMEM_FLOATS (32768 + 8192 + 16384 + 256 + 256 + 32)
#define REC_SMEM_BYTES  (REC_SMEM_FLOATS * 4)   // 231,552 < 232,448 max

__device__ __forceinline__ void grid_sync(unsigned target)
{
    __syncthreads();
    if (threadIdx.x == 0) {
        asm volatile("red.release.gpu.global.add.u32 [%0], %1;"
                     :: "l"(&g_bar), "r"(1u) : "memory");
        unsigned v;
        do {
            asm volatile("ld.acquire.gpu.global.u32 %0, [%1];"
                         : "=r"(v) : "l"(&g_bar) : "memory");
        } while (v < target);
    }
    __syncthreads();
}

__global__ void __launch_bounds__(512) rec_kernel(
    const float* __restrict__ xproj,   // [16384,4096] (bias already added)
    const float* __restrict__ W,       // [2048,4096]; rows 1024.. are Wh
    const int*   __restrict__ lengths, // [32]
    float*       __restrict__ out_h,   // [32,512,1024]
    float*       __restrict__ hc_final)// null, or [h1 | c1]
{
    extern __shared__ __align__(16) float sm[];
    float* Wsh   = sm;                   // [k][j], j = g*8+jh, 1024*32
    float* hsh   = Wsh + 32768;          // [kk<256][b] active quarter
    float* zsh   = hsh + 8192;           // [w(16)][g(4)][b*8+jh] partials
    float* csh   = zsh + 16384;
    float* hown  = csh + 256;
    int*   lensh = (int*)(hown + 256);

    const int tid = threadIdx.x;
    const int blk = blockIdx.x;
    const int b   = tid & 31;            // lane = batch
    const int w   = tid >> 5;            // 0..15 -> 16-k slice per quarter

    // Wh slice into smem: Wsh[k][g*8+jh] = W[1024+k][g*1024 + blk*8 + jh]
    for (int i = tid; i < 32768; i += 512) {
        int k = i >> 5, j = i & 31;
        int g = j >> 3, jh = j & 7;
        Wsh[i] = W[(size_t)(HS + k) * GSZ + g * HS + blk * 8 + jh];
    }
    if (tid < 32) lensh[tid] = lengths[tid];
    if (tid < 256) {
        csh[tid] = 0.0f; hown[tid] = 0.0f;
        __stcg(&g_hbuf[blk * 256 + tid], 0.0f);   // h(0) = 0 slice
    }

    unsigned bar_t = NBLK;
    grid_sync(bar_t);

    int cur = 0;
    const ulonglong2* Wsh2 = (const ulonglong2*)Wsh;  // 8 per k-row

    for (int t = 0; t < TSTEP; t++) {
        const float4* hq4 = (const float4*)(g_hbuf + (size_t)cur * 32768);
        float4* hsh4 = (float4*)hsh;

        // hoisted xproj loads, consumed in cell phase (~latency hidden)
        float xz[4];
        if (tid < 256) {
            int bu = tid >> 3, jh = tid & 7;
            const float* xp =
                xproj + ((size_t)(bu * TSTEP + t)) * GSZ + blk * 8 + jh;
#pragma unroll
            for (int g = 0; g < 4; g++) xz[g] = __ldcg(xp + g * HS);
        }

        u64 acc[16];
#pragma unroll
        for (int i = 0; i < 16; i++) acc[i] = 0ull;

        // stage quarter 0 (2048 float4, 4/thread)
#pragma unroll
        for (int r = 0; r < 4; r++)
            hsh4[tid + r * 512] = __ldcg(hq4 + tid + r * 512);
        __syncthreads();

#pragma unroll
        for (int q = 0; q < 4; q++) {
            // prefetch quarter q+1 into regs (overlaps compute)
            float4 stg[4];
            if (q < 3) {
#pragma unroll
                for (int r = 0; r < 4; r++)
                    stg[r] = __ldcg(hq4 + (q + 1) * 2048 + tid + r * 512);
            }

            // compute: this warp's 16-k slice, all 32 gate cols
            const float* hb = hsh + w * 16 * 32 + b;
            const ulonglong2* Wr = Wsh2 + (size_t)(q * 256 + w * 16) * 8;
#pragma unroll
            for (int kk = 0; kk < 16; kk++) {
                float hv = hb[kk * 32];
                u64 h2 = pack2(hv, hv);
                const ulonglong2* Wk = Wr + kk * 8;
#pragma unroll
                for (int j = 0; j < 8; j++) {
                    ulonglong2 wp = Wk[j];
                    acc[2 * j]     = ffma2(h2, wp.x, acc[2 * j]);
                    acc[2 * j + 1] = ffma2(h2, wp.y, acc[2 * j + 1]);
                }
            }

            if (q < 3) {
                __syncthreads();
#pragma unroll
                for (int r = 0; r < 4; r++)
                    hsh4[tid + r * 512] = stg[r];
                __syncthreads();
            }
        }

        // store partials: zsh[w][g][b*8 + jh], as float4 pairs (cols 4j..4j+3)
        {
            float4* z4 = (float4*)zsh;
#pragma unroll
            for (int j = 0; j < 8; j++) {
                int col0 = 4 * j;
                int g = col0 >> 3, jh0 = col0 & 7;
                float4 v;
                v.x = __ull2float_ru(0);  // placeholder overwritten below
                float a0, a1, a2, a3;
                unpack2(acc[2 * j], a0, a1);
                unpack2(acc[2 * j + 1], a2, a3);
                v = make_float4(a0, a1, a2, a3);
                z4[(w * 1024 + g * 256 + b * 8 + jh0) >> 2] = v;
            }
        }
        __syncthreads();

        // cell update: 256 units, threads 0..255
        const int nxt = cur ^ 1;
        if (tid < 256) {
            int u  = tid;
            int bu = u >> 3, jh = u & 7;
            float zq[4];
#pragma unroll
            for (int g = 0; g < 4; g++) {
                float s = xz[g];
#pragma unroll
                for (int c = 0; c < 16; c++)
                    s += zsh[c * 1024 + g * 256 + u];
                zq[g] = s;
            }
            float cp = csh[u];
            float cn = sigf(zq[2] + 1.0f) * cp + sigf(zq[0]) * tanhf(zq[1]);
            float hn = sigf(zq[3]) * tanhf(cn);
            bool mask = (t < lensh[bu]);
            float hk = mask ? hn : hown[u];
            float ck = mask ? cn : cp;
            csh[u]  = ck;
            hown[u] = hk;
            int kg = blk * 8 + jh;
            out_h[((size_t)bu * TSTEP + t) * HS + kg] = mask ? hn : 0.0f;
            __stcg(&g_hbuf[(size_t)nxt * 32768 + kg * 32 + bu], hk);
            if (hc_final != nullptr && t == TSTEP - 1) {
                hc_final[(size_t)bu * HS + kg]         = hk;
                hc_final[32768 + (size_t)bu * HS + kg] = ck;
            }
        }

        bar_t += NBLK;
        grid_sync(bar_t);
        cur = nxt;
    }
}

// ---------------------------------------------------------------------------
extern "C" void kernel_launch(void* const* d_in, const int* in_sizes, int n_in,
                              void* d_out, int out_size)
{
    const float* x       = (const float*)d_in[0];
    const int*   lengths = (const int*)  d_in[1];
    const float* W0      = (const float*)d_in[2];
    const float* b0      = (const float*)d_in[3];
    const float* W1      = (const float*)d_in[4];
    const float* b1      = (const float*)d_in[5];
    float*       out     = (float*)d_out;

    (void)in_sizes; (void)n_in; (void)out_size;

    cudaFuncSetAttribute(rec_kernel,
                         cudaFuncAttributeMaxDynamicSharedMemorySize,
                         REC_SMEM_BYTES);

    float* xproj = nullptr;
    float* out0  = nullptr;
    cudaGetSymbolAddress((void**)&xproj, g_xproj);
    cudaGetSymbolAddress((void**)&out0,  g_out0);

    dim3 ggrid(GSZ / GBN, MROWS / GBM);  // (64, 128)

    // Layer 0
    gemm_kernel<<<ggrid, 256>>>(x, W0, b0, xproj);
    init_bar_kernel<<<1, 1>>>();
    rec_kernel<<<NBLK, 512, REC_SMEM_BYTES>>>(xproj, W0, lengths, out0, nullptr);

    // Layer 1
    gemm_kernel<<<ggrid, 256>>>(out0, W1, b1, xproj);
    init_bar_kernel<<<1, 1>>>();
    rec_kernel<<<NBLK, 512, REC_SMEM_BYTES>>>(xproj, W1, lengths,
                                              out, out + (size_t)MROWS * HS);
}

// round 9
// speedup vs baseline: 1.1488x; 1.1037x over previous
#include <cuda_runtime.h>
#include <cuda_bf16.h>
#include <cstddef>

// ---------------------------------------------------------------------------
// 2-layer TF LSTM: B=32, T=512, INSZ=HSZ=1024, G=4096.
// Output: concat(out1[32,512,1024], h1[32,1024], c1[32,1024]) f32.
// ---------------------------------------------------------------------------

#define BSZ   32
#define TSTEP 512
#define HS    1024
#define GSZ   4096
#define MROWS (BSZ * TSTEP)      // 16384
#define NBLK  128                // persistent CTAs for recurrence

typedef unsigned long long u64;

// ----------------------------- device scratch ------------------------------
__device__ __align__(16) float g_xproj[(size_t)MROWS * GSZ];  // 256 MB
__device__ __align__(16) float g_out0 [(size_t)MROWS * HS];   //  64 MB
__device__ __align__(16) float g_hbuf [2 * HS * BSZ];         // ping-pong h, [buf][k][b]
__device__ unsigned g_bar;

// ----------------------------- f32x2 helpers -------------------------------
__device__ __forceinline__ u64 pack2(float lo, float hi) {
    u64 r; asm("mov.b64 %0, {%1, %2};" : "=l"(r) : "f"(lo), "f"(hi)); return r;
}
__device__ __forceinline__ void unpack2(u64 v, float& lo, float& hi) {
    asm("mov.b64 {%0, %1}, %2;" : "=f"(lo), "=f"(hi) : "l"(v));
}
__device__ __forceinline__ u64 ffma2(u64 a, u64 b, u64 c) {
    u64 d; asm("fma.rn.f32x2 %0, %1, %2, %3;" : "=l"(d) : "l"(a), "l"(b), "l"(c)); return d;
}
__device__ __forceinline__ float sigf(float x) { return 1.0f / (1.0f + __expf(-x)); }

// ----------------------------- barrier reset -------------------------------
__global__ void init_bar_kernel() { g_bar = 0u; }

// ---------------------------------------------------------------------------
// GEMM (measured-stable, fma=66.6%): C = A[.,0:1024] @ W[0:1024,.] + bias
// Tile 128(m) x 64(n), BK=16, 256 threads, microtile 8x4 with f32x2 pairs.
// ---------------------------------------------------------------------------
#define GBM 128
#define GBN 64
#define GBK 16

__global__ void __launch_bounds__(256) gemm_kernel(
    const float* __restrict__ A, const float* __restrict__ W,
    const float* __restrict__ bias, float* __restrict__ C)
{
    __shared__ float Ash[GBK][132];
    __shared__ __align__(16) float Bsh[GBK][GBN];

    const int tid = threadIdx.x;
    const int m0  = blockIdx.y * GBM;
    const int n0  = blockIdx.x * GBN;
    const int tm  = tid >> 4;
    const int tn  = tid & 15;

    u64 acc[8][2];
    {
        float4 bv = *(const float4*)(bias + n0 + tn * 4);
        u64 b01 = pack2(bv.x, bv.y), b23 = pack2(bv.z, bv.w);
#pragma unroll
        for (int i = 0; i < 8; i++) { acc[i][0] = b01; acc[i][1] = b23; }
    }

    for (int k0 = 0; k0 < HS; k0 += GBK) {
#pragma unroll
        for (int r = 0; r < 2; r++) {
            int f = tid + r * 256;
            int m = f >> 2, kq = (f & 3) * 4;
            float4 av = *(const float4*)(A + (size_t)(m0 + m) * HS + k0 + kq);
            Ash[kq + 0][m] = av.x; Ash[kq + 1][m] = av.y;
            Ash[kq + 2][m] = av.z; Ash[kq + 3][m] = av.w;
        }
        {
            int k = tid >> 4, n4 = (tid & 15) * 4;
            *(float4*)&Bsh[k][n4] =
                *(const float4*)(W + (size_t)(k0 + k) * GSZ + n0 + n4);
        }
        __syncthreads();

#pragma unroll
        for (int kk = 0; kk < GBK; kk++) {
            float4 a0 = *(const float4*)&Ash[kk][tm * 8];
            float4 a1 = *(const float4*)&Ash[kk][tm * 8 + 4];
            float4 b4 = *(const float4*)&Bsh[kk][tn * 4];
            u64 w01 = pack2(b4.x, b4.y), w23 = pack2(b4.z, b4.w);
            float am[8] = {a0.x, a0.y, a0.z, a0.w, a1.x, a1.y, a1.z, a1.w};
#pragma unroll
            for (int i = 0; i < 8; i++) {
                u64 ai = pack2(am[i], am[i]);
                acc[i][0] = ffma2(ai, w01, acc[i][0]);
                acc[i][1] = ffma2(ai, w23, acc[i][1]);
            }
        }
        __syncthreads();
    }

#pragma unroll
    for (int i = 0; i < 8; i++) {
        float x0, x1, x2, x3;
        unpack2(acc[i][0], x0, x1);
        unpack2(acc[i][1], x2, x3);
        *(float4*)(C + (size_t)(m0 + tm * 8 + i) * GSZ + n0 + tn * 4) =
            make_float4(x0, x1, x2, x3);
    }
}

// ---------------------------------------------------------------------------
// Recurrence: persistent, 128 CTAs x 512 threads (16 warps, 4/SMSP).
// CTA owns 8 hidden cols -> 32 gate cols. Warp w covers all 32 gate cols for
// k in {q*256 + w*16 + i : q<4, i<16}; lane = batch.
// h is NOT staged through smem: each thread holds its 64 h values in
// registers, loaded coalesced from L2 in a rolling 2-chunk pipeline.
// Per-step syncs: grid_sync (2 bars) + 1 partials bar = 3 total.
// ---------------------------------------------------------------------------
// smem floats: Wsh 32768 | zsh 16384 | csh 256 | hown 256 | len 32
#define REC_SMEM_FLOATS (32768 + 16384 + 256 + 256 + 32)
#define REC_SMEM_BYTES  (REC_SMEM_FLOATS * 4)   // 198,784 B

__device__ __forceinline__ void grid_sync(unsigned target)
{
    __syncthreads();
    if (threadIdx.x == 0) {
        asm volatile("red.release.gpu.global.add.u32 [%0], %1;"
                     :: "l"(&g_bar), "r"(1u) : "memory");
        unsigned v;
        do {
            asm volatile("ld.acquire.gpu.global.u32 %0, [%1];"
                         : "=r"(v) : "l"(&g_bar) : "memory");
        } while (v < target);
    }
    __syncthreads();
}

__global__ void __launch_bounds__(512) rec_kernel(
    const float* __restrict__ xproj,   // [16384,4096] (bias already added)
    const float* __restrict__ W,       // [2048,4096]; rows 1024.. are Wh
    const int*   __restrict__ lengths, // [32]
    float*       __restrict__ out_h,   // [32,512,1024]
    float*       __restrict__ hc_final)// null, or [h1 | c1]
{
    extern __shared__ __align__(16) float sm[];
    float* Wsh   = sm;                   // [k][j], j = g*8+jh, 1024*32
    float* zsh   = Wsh + 32768;          // [w(16)][g(4)][b*8+jh] partials
    float* csh   = zsh + 16384;
    float* hown  = csh + 256;
    int*   lensh = (int*)(hown + 256);

    const int tid = threadIdx.x;
    const int blk = blockIdx.x;
    const int b   = tid & 31;            // lane = batch
    const int w   = tid >> 5;            // 0..15

    // Wh slice into smem: Wsh[k][g*8+jh] = W[1024+k][g*1024 + blk*8 + jh]
    for (int i = tid; i < 32768; i += 512) {
        int k = i >> 5, j = i & 31;
        int g = j >> 3, jh = j & 7;
        Wsh[i] = W[(size_t)(HS + k) * GSZ + g * HS + blk * 8 + jh];
    }
    if (tid < 32) lensh[tid] = lengths[tid];
    if (tid < 256) {
        csh[tid] = 0.0f; hown[tid] = 0.0f;
        __stcg(&g_hbuf[blk * 256 + tid], 0.0f);   // h(0) = 0 slice
    }

    unsigned bar_t = NBLK;
    grid_sync(bar_t);

    int cur = 0;
    const ulonglong2* Wsh2 = (const ulonglong2*)Wsh;  // 8 per k-row

    for (int t = 0; t < TSTEP; t++) {
        // hoisted xproj loads, consumed in cell phase (fully hidden)
        float xz[4];
        if (tid < 256) {
            int bu = tid >> 3, jh = tid & 7;
            const float* xp =
                xproj + ((size_t)(bu * TSTEP + t)) * GSZ + blk * 8 + jh;
#pragma unroll
            for (int g = 0; g < 4; g++) xz[g] = __ldcg(xp + g * HS);
        }

        u64 acc[16];
#pragma unroll
        for (int i = 0; i < 16; i++) acc[i] = 0ull;

        // h in registers: rolling 2-chunk pipeline over 4 chunks of 16 k
        const float* hsrc = g_hbuf + (size_t)cur * 32768 + w * 16 * 32 + b;
        float hr[2][16];
#pragma unroll
        for (int i = 0; i < 16; i++)
            hr[0][i] = __ldcg(hsrc + i * 32);

#pragma unroll
        for (int q = 0; q < 4; q++) {
            if (q < 3) {
                const float* nsrc = hsrc + (q + 1) * 256 * 32;
#pragma unroll
                for (int i = 0; i < 16; i++)
                    hr[(q + 1) & 1][i] = __ldcg(nsrc + i * 32);
            }

            const ulonglong2* Wr = Wsh2 + (size_t)(q * 256 + w * 16) * 8;
#pragma unroll
            for (int kk = 0; kk < 16; kk++) {
                float hv = hr[q & 1][kk];
                u64 h2 = pack2(hv, hv);
                const ulonglong2* Wk = Wr + kk * 8;
#pragma unroll
                for (int j = 0; j < 8; j++) {
                    ulonglong2 wp = Wk[j];
                    acc[2 * j]     = ffma2(h2, wp.x, acc[2 * j]);
                    acc[2 * j + 1] = ffma2(h2, wp.y, acc[2 * j + 1]);
                }
            }
        }

        // store partials: zsh[w][g][b*8+jh] (cols 4j..4j+3 per float4)
        {
            float4* z4 = (float4*)zsh;
#pragma unroll
            for (int j = 0; j < 8; j++) {
                int col0 = 4 * j;
                int g = col0 >> 3, jh0 = col0 & 7;
                float a0, a1, a2, a3;
                unpack2(acc[2 * j], a0, a1);
                unpack2(acc[2 * j + 1], a2, a3);
                z4[(w * 1024 + g * 256 + b * 8 + jh0) >> 2] =
                    make_float4(a0, a1, a2, a3);
            }
        }
        __syncthreads();

        // cell update: 256 units, threads 0..255
        const int nxt = cur ^ 1;
        if (tid < 256) {
            int u  = tid;
            int bu = u >> 3, jh = u & 7;
            float zq[4];
#pragma unroll
            for (int g = 0; g < 4; g++) {
                float s = xz[g];
#pragma unroll
                for (int c = 0; c < 16; c++)
                    s += zsh[c * 1024 + g * 256 + u];
                zq[g] = s;
            }
            float cp = csh[u];
            float cn = sigf(zq[2] + 1.0f) * cp + sigf(zq[0]) * tanhf(zq[1]);
            float hn = sigf(zq[3]) * tanhf(cn);
            bool mask = (t < lensh[bu]);
            float hk = mask ? hn : hown[u];
            float ck = mask ? cn : cp;
            csh[u]  = ck;
            hown[u] = hk;
            int kg = blk * 8 + jh;
            out_h[((size_t)bu * TSTEP + t) * HS + kg] = mask ? hn : 0.0f;
            __stcg(&g_hbuf[(size_t)nxt * 32768 + kg * 32 + bu], hk);
            if (hc_final != nullptr && t == TSTEP - 1) {
                hc_final[(size_t)bu * HS + kg]         = hk;
                hc_final[32768 + (size_t)bu * HS + kg] = ck;
            }
        }

        bar_t += NBLK;
        grid_sync(bar_t);
        cur = nxt;
    }
}

// ---------------------------------------------------------------------------
extern "C" void kernel_launch(void* const* d_in, const int* in_sizes, int n_in,
                              void* d_out, int out_size)
{
    const float* x       = (const float*)d_in[0];
    const int*   lengths = (const int*)  d_in[1];
    const float* W0      = (const float*)d_in[2];
    const float* b0      = (const float*)d_in[3];
    const float* W1      = (const float*)d_in[4];
    const float* b1      = (const float*)d_in[5];
    float*       out     = (float*)d_out;

    (void)in_sizes; (void)n_in; (void)out_size;

    cudaFuncSetAttribute(rec_kernel,
                         cudaFuncAttributeMaxDynamicSharedMemorySize,
                         REC_SMEM_BYTES);

    float* xproj = nullptr;
    float* out0  = nullptr;
    cudaGetSymbolAddress((void**)&xproj, g_xproj);
    cudaGetSymbolAddress((void**)&out0,  g_out0);

    dim3 ggrid(GSZ / GBN, MROWS / GBM);  // (64, 128)

    // Layer 0
    gemm_kernel<<<ggrid, 256>>>(x, W0, b0, xproj);
    init_bar_kernel<<<1, 1>>>();
    rec_kernel<<<NBLK, 512, REC_SMEM_BYTES>>>(xproj, W0, lengths, out0, nullptr);

    // Layer 1
    gemm_kernel<<<ggrid, 256>>>(out0, W1, b1, xproj);
    init_bar_kernel<<<1, 1>>>();
    rec_kernel<<<NBLK, 512, REC_SMEM_BYTES>>>(xproj, W1, lengths,
                                              out, out + (size_t)MROWS * HS);
}

// round 11
// speedup vs baseline: 1.1646x; 1.0138x over previous
#include <cuda_runtime.h>
#include <cuda_bf16.h>
#include <mma.h>
#include <cstdint>
#include <cstddef>

using namespace nvcuda;

// ---------------------------------------------------------------------------
// 2-layer TF LSTM: B=32, T=512, INSZ=HSZ=1024, G=4096.
// Output: concat(out1[32,512,1024], h1[32,1024], c1[32,1024]) f32.
// R11: projection GEMM on tensor pipe via wmma bf16 split-precision (3-term,
//      baseline PTX -> valid for sm_103 target); recurrence = R9 (proven).
// ---------------------------------------------------------------------------

#define BSZ   32
#define TSTEP 512
#define HS    1024
#define GSZ   4096
#define MROWS (BSZ * TSTEP)      // 16384
#define NBLK  128                // persistent CTAs for recurrence

typedef unsigned long long u64;

// ----------------------------- device scratch ------------------------------
__device__ __align__(16) float g_xproj[(size_t)MROWS * GSZ];      // 256 MB
__device__ __align__(16) float g_out0 [(size_t)MROWS * HS];       //  64 MB
__device__ __align__(16) float g_hbuf [2 * HS * BSZ];
__device__ __align__(16) __nv_bfloat16 g_ah[(size_t)MROWS * HS];  // 32 MB
__device__ __align__(16) __nv_bfloat16 g_al[(size_t)MROWS * HS];  // 32 MB
__device__ __align__(16) __nv_bfloat16 g_wh[(size_t)HS * GSZ];    //  8 MB
__device__ __align__(16) __nv_bfloat16 g_wl[(size_t)HS * GSZ];    //  8 MB
__device__ unsigned g_bar;

// ----------------------------- f32x2 helpers -------------------------------
__device__ __forceinline__ u64 pack2(float lo, float hi) {
    u64 r; asm("mov.b64 %0, {%1, %2};" : "=l"(r) : "f"(lo), "f"(hi)); return r;
}
__device__ __forceinline__ void unpack2(u64 v, float& lo, float& hi) {
    asm("mov.b64 {%0, %1}, %2;" : "=f"(lo), "=f"(hi) : "l"(v));
}
__device__ __forceinline__ u64 ffma2(u64 a, u64 b, u64 c) {
    u64 d; asm("fma.rn.f32x2 %0, %1, %2, %3;" : "=l"(d) : "l"(a), "l"(b), "l"(c)); return d;
}
__device__ __forceinline__ float sigf(float x) { return 1.0f / (1.0f + __expf(-x)); }

// ----------------------------- barrier reset -------------------------------
__global__ void init_bar_kernel() { g_bar = 0u; }

// ---------------------------------------------------------------------------
// split_kernel: fp32 [N] -> bf16 hi/lo (hi = rn(x), lo = rn(x - hi))
// ---------------------------------------------------------------------------
__global__ void __launch_bounds__(256) split_kernel(
    const float* __restrict__ in, __nv_bfloat16* __restrict__ hi,
    __nv_bfloat16* __restrict__ lo)
{
    size_t i = ((size_t)blockIdx.x * 256 + threadIdx.x) * 4;
    float4 v = *(const float4*)(in + i);
    __nv_bfloat16 h0 = __float2bfloat16(v.x);
    __nv_bfloat16 h1 = __float2bfloat16(v.y);
    __nv_bfloat16 h2 = __float2bfloat16(v.z);
    __nv_bfloat16 h3 = __float2bfloat16(v.w);
    __nv_bfloat16 l0 = __float2bfloat16(v.x - __bfloat162float(h0));
    __nv_bfloat16 l1 = __float2bfloat16(v.y - __bfloat162float(h1));
    __nv_bfloat16 l2 = __float2bfloat16(v.z - __bfloat162float(h2));
    __nv_bfloat16 l3 = __float2bfloat16(v.w - __bfloat162float(h3));
    __nv_bfloat162* H = (__nv_bfloat162*)(hi + i);
    __nv_bfloat162* L = (__nv_bfloat162*)(lo + i);
    H[0] = __halves2bfloat162(h0, h1); H[1] = __halves2bfloat162(h2, h3);
    L[0] = __halves2bfloat162(l0, l1); L[1] = __halves2bfloat162(l2, l3);
}

// ---------------------------------------------------------------------------
// mm_kernel (wmma bf16): C[m][n] = sum_seg A_seg[m][k]*B_seg[k][n] + bias[n]
// Segments: (Ah,Wh), (Al,Wh), (Ah,Wl).  A row-major [M,1024], B row-major
// [1024,4096].  CTA tile 128m x 64n, BK=32, 256 thr, 8 warps (4m x 2n),
// warp tile 32x32 = 2x2 wmma m16n16k16 frags, fp32 accumulators.
// ---------------------------------------------------------------------------
#define MM_LDA 40
#define MM_LDB 72
#define MM_ASH_BYTES (128 * MM_LDA * 2)     // 10240
#define MM_SMEM      32768                  // reused as 128x64 f32 out tile

__global__ void __launch_bounds__(256) mm_kernel(
    const __nv_bfloat16* __restrict__ Ah, const __nv_bfloat16* __restrict__ Al,
    const __nv_bfloat16* __restrict__ Bh, const __nv_bfloat16* __restrict__ Bl,
    const float* __restrict__ bias, float* __restrict__ C)
{
    extern __shared__ __align__(16) char smem[];
    __nv_bfloat16* Ash = (__nv_bfloat16*)smem;                    // [128][40]
    __nv_bfloat16* Bsh = (__nv_bfloat16*)(smem + MM_ASH_BYTES);   // [32][72]
    float* Csh = (float*)smem;                                    // [128][64]
    __shared__ float biasS[64];

    const int tid = threadIdx.x;
    const int wid = tid >> 5;
    const int wm = wid >> 1, wn = wid & 1;
    const int m0 = blockIdx.y * 128;
    const int n0 = blockIdx.x * 64;

    if (tid < 64) biasS[tid] = bias[n0 + tid];

    wmma::fragment<wmma::accumulator, 16, 16, 16, float> acc[2][2];
#pragma unroll
    for (int i = 0; i < 2; ++i)
#pragma unroll
        for (int j = 0; j < 2; ++j)
            wmma::fill_fragment(acc[i][j], 0.0f);

    const __nv_bfloat16* Asrc[3] = { Ah, Al, Ah };
    const __nv_bfloat16* Bsrc[3] = { Bh, Bh, Bl };

#pragma unroll 1
    for (int seg = 0; seg < 3; ++seg) {
        const __nv_bfloat16* Ag = Asrc[seg];
        const __nv_bfloat16* Bg = Bsrc[seg];
#pragma unroll 1
        for (int k0 = 0; k0 < HS; k0 += 32) {
            __syncthreads();   // protect previous chunk's reads
            // A tile: 128 x 32 bf16 = 512 uint4, 2 per thread
#pragma unroll
            for (int r = 0; r < 2; ++r) {
                int f = tid + r * 256;
                int row = f >> 2, c = (f & 3) * 8;
                *(uint4*)(Ash + row * MM_LDA + c) =
                    *(const uint4*)(Ag + (size_t)(m0 + row) * HS + k0 + c);
            }
            // B tile: 32 x 64 bf16 = 256 uint4, 1 per thread
            {
                int row = tid >> 3, c = (tid & 7) * 8;
                *(uint4*)(Bsh + row * MM_LDB + c) =
                    *(const uint4*)(Bg + (size_t)(k0 + row) * GSZ + n0 + c);
            }
            __syncthreads();

#pragma unroll
            for (int ks = 0; ks < 2; ++ks) {
                wmma::fragment<wmma::matrix_a, 16, 16, 16, __nv_bfloat16,
                               wmma::row_major> af[2];
                wmma::fragment<wmma::matrix_b, 16, 16, 16, __nv_bfloat16,
                               wmma::row_major> bf[2];
                wmma::load_matrix_sync(af[0],
                    Ash + (wm * 32) * MM_LDA + ks * 16, MM_LDA);
                wmma::load_matrix_sync(af[1],
                    Ash + (wm * 32 + 16) * MM_LDA + ks * 16, MM_LDA);
                wmma::load_matrix_sync(bf[0],
                    Bsh + (ks * 16) * MM_LDB + wn * 32, MM_LDB);
                wmma::load_matrix_sync(bf[1],
                    Bsh + (ks * 16) * MM_LDB + wn * 32 + 16, MM_LDB);
#pragma unroll
                for (int i = 0; i < 2; ++i)
#pragma unroll
                    for (int j = 0; j < 2; ++j)
                        wmma::mma_sync(acc[i][j], af[i], bf[j], acc[i][j]);
            }
        }
    }

    __syncthreads();
#pragma unroll
    for (int i = 0; i < 2; ++i)
#pragma unroll
        for (int j = 0; j < 2; ++j)
            wmma::store_matrix_sync(
                Csh + (size_t)(wm * 32 + i * 16) * 64 + wn * 32 + j * 16,
                acc[i][j], 64, wmma::mem_row_major);
    __syncthreads();

    // bias + writeout: 128x64 f32 = 2048 float4, 8 per thread
#pragma unroll
    for (int r = 0; r < 8; ++r) {
        int f = tid + r * 256;
        int row = f >> 4, c = (f & 15) * 4;
        float4 v = *(float4*)(Csh + row * 64 + c);
        v.x += biasS[c + 0]; v.y += biasS[c + 1];
        v.z += biasS[c + 2]; v.w += biasS[c + 3];
        *(float4*)(C + (size_t)(m0 + row) * GSZ + n0 + c) = v;
    }
}

// ---------------------------------------------------------------------------
// Recurrence (unchanged from R9): persistent, 128 CTAs x 512 threads.
// ---------------------------------------------------------------------------
#define REC_SMEM_FLOATS (32768 + 16384 + 256 + 256 + 32)
#define REC_SMEM_BYTES  (REC_SMEM_FLOATS * 4)

__device__ __forceinline__ void grid_sync(unsigned target)
{
    __syncthreads();
    if (threadIdx.x == 0) {
        asm volatile("red.release.gpu.global.add.u32 [%0], %1;"
                     :: "l"(&g_bar), "r"(1u) : "memory");
        unsigned v;
        do {
            asm volatile("ld.acquire.gpu.global.u32 %0, [%1];"
                         : "=r"(v) : "l"(&g_bar) : "memory");
        } while (v < target);
    }
    __syncthreads();
}

__global__ void __launch_bounds__(512) rec_kernel(
    const float* __restrict__ xproj,
    const float* __restrict__ W,
    const int*   __restrict__ lengths,
    float*       __restrict__ out_h,
    float*       __restrict__ hc_final)
{
    extern __shared__ __align__(16) float sm[];
    float* Wsh   = sm;
    float* zsh   = Wsh + 32768;
    float* csh   = zsh + 16384;
    float* hown  = csh + 256;
    int*   lensh = (int*)(hown + 256);

    const int tid = threadIdx.x;
    const int blk = blockIdx.x;
    const int b   = tid & 31;
    const int w   = tid >> 5;

    for (int i = tid; i < 32768; i += 512) {
        int k = i >> 5, j = i & 31;
        int g = j >> 3, jh = j & 7;
        Wsh[i] = W[(size_t)(HS + k) * GSZ + g * HS + blk * 8 + jh];
    }
    if (tid < 32) lensh[tid] = lengths[tid];
    if (tid < 256) {
        csh[tid] = 0.0f; hown[tid] = 0.0f;
        __stcg(&g_hbuf[blk * 256 + tid], 0.0f);
    }

    unsigned bar_t = NBLK;
    grid_sync(bar_t);

    int cur = 0;
    const ulonglong2* Wsh2 = (const ulonglong2*)Wsh;

    for (int t = 0; t < TSTEP; t++) {
        float xz[4];
        if (tid < 256) {
            int bu = tid >> 3, jh = tid & 7;
            const float* xp =
                xproj + ((size_t)(bu * TSTEP + t)) * GSZ + blk * 8 + jh;
#pragma unroll
            for (int g = 0; g < 4; g++) xz[g] = __ldcg(xp + g * HS);
        }

        u64 acc[16];
#pragma unroll
        for (int i = 0; i < 16; i++) acc[i] = 0ull;

        const float* hsrc = g_hbuf + (size_t)cur * 32768 + w * 16 * 32 + b;
        float hr[2][16];
#pragma unroll
        for (int i = 0; i < 16; i++)
            hr[0][i] = __ldcg(hsrc + i * 32);

#pragma unroll
        for (int q = 0; q < 4; q++) {
            if (q < 3) {
                const float* nsrc = hsrc + (q + 1) * 256 * 32;
#pragma unroll
                for (int i = 0; i < 16; i++)
                    hr[(q + 1) & 1][i] = __ldcg(nsrc + i * 32);
            }

            const ulonglong2* Wr = Wsh2 + (size_t)(q * 256 + w * 16) * 8;
#pragma unroll
            for (int kk = 0; kk < 16; kk++) {
                float hv = hr[q & 1][kk];
                u64 h2 = pack2(hv, hv);
                const ulonglong2* Wk = Wr + kk * 8;
#pragma unroll
                for (int j = 0; j < 8; j++) {
                    ulonglong2 wp = Wk[j];
                    acc[2 * j]     = ffma2(h2, wp.x, acc[2 * j]);
                    acc[2 * j + 1] = ffma2(h2, wp.y, acc[2 * j + 1]);
                }
            }
        }

        {
            float4* z4 = (float4*)zsh;
#pragma unroll
            for (int j = 0; j < 8; j++) {
                int col0 = 4 * j;
                int g = col0 >> 3, jh0 = col0 & 7;
                float a0, a1, a2, a3;
                unpack2(acc[2 * j], a0, a1);
                unpack2(acc[2 * j + 1], a2, a3);
                z4[(w * 1024 + g * 256 + b * 8 + jh0) >> 2] =
                    make_float4(a0, a1, a2, a3);
            }
        }
        __syncthreads();

        const int nxt = cur ^ 1;
        if (tid < 256) {
            int u  = tid;
            int bu = u >> 3, jh = u & 7;
            float zq[4];
#pragma unroll
            for (int g = 0; g < 4; g++) {
                float s = xz[g];
#pragma unroll
                for (int c = 0; c < 16; c++)
                    s += zsh[c * 1024 + g * 256 + u];
                zq[g] = s;
            }
            float cp = csh[u];
            float cn = sigf(zq[2] + 1.0f) * cp + sigf(zq[0]) * tanhf(zq[1]);
            float hn = sigf(zq[3]) * tanhf(cn);
            bool mask = (t < lensh[bu]);
            float hk = mask ? hn : hown[u];
            float ck = mask ? cn : cp;
            csh[u]  = ck;
            hown[u] = hk;
            int kg = blk * 8 + jh;
            out_h[((size_t)bu * TSTEP + t) * HS + kg] = mask ? hn : 0.0f;
            __stcg(&g_hbuf[(size_t)nxt * 32768 + kg * 32 + bu], hk);
            if (hc_final != nullptr && t == TSTEP - 1) {
                hc_final[(size_t)bu * HS + kg]         = hk;
                hc_final[32768 + (size_t)bu * HS + kg] = ck;
            }
        }

        bar_t += NBLK;
        grid_sync(bar_t);
        cur = nxt;
    }
}

// ---------------------------------------------------------------------------
extern "C" void kernel_launch(void* const* d_in, const int* in_sizes, int n_in,
                              void* d_out, int out_size)
{
    const float* x       = (const float*)d_in[0];
    const int*   lengths = (const int*)  d_in[1];
    const float* W0      = (const float*)d_in[2];
    const float* b0      = (const float*)d_in[3];
    const float* W1      = (const float*)d_in[4];
    const float* b1      = (const float*)d_in[5];
    float*       out     = (float*)d_out;

    (void)in_sizes; (void)n_in; (void)out_size;

    cudaFuncSetAttribute(rec_kernel,
                         cudaFuncAttributeMaxDynamicSharedMemorySize,
                         REC_SMEM_BYTES);

    float* xproj = nullptr;
    float* out0  = nullptr;
    __nv_bfloat16 *ah, *al, *wh, *wl;
    cudaGetSymbolAddress((void**)&xproj, g_xproj);
    cudaGetSymbolAddress((void**)&out0,  g_out0);
    cudaGetSymbolAddress((void**)&ah, g_ah);
    cudaGetSymbolAddress((void**)&al, g_al);
    cudaGetSymbolAddress((void**)&wh, g_wh);
    cudaGetSymbolAddress((void**)&wl, g_wl);

    dim3 mgrid(GSZ / 64, MROWS / 128);   // (64, 128)

    // Layer 0
    split_kernel<<<(MROWS * HS) / 1024, 256>>>(x, ah, al);
    split_kernel<<<(HS * GSZ) / 1024, 256>>>(W0, wh, wl);   // W0 rows 0..1023
    mm_kernel<<<mgrid, 256, MM_SMEM>>>(ah, al, wh, wl, b0, xproj);
    init_bar_kernel<<<1, 1>>>();
    rec_kernel<<<NBLK, 512, REC_SMEM_BYTES>>>(xproj, W0, lengths, out0, nullptr);

    // Layer 1
    split_kernel<<<(MROWS * HS) / 1024, 256>>>(out0, ah, al);
    split_kernel<<<(HS * GSZ) / 1024, 256>>>(W1, wh, wl);
    mm_kernel<<<mgrid, 256, MM_SMEM>>>(ah, al, wh, wl, b1, xproj);
    init_bar_kernel<<<1, 1>>>();
    rec_kernel<<<NBLK, 512, REC_SMEM_BYTES>>>(xproj, W1, lengths,
                                              out, out + (size_t)MROWS * HS);
}

// round 12
// speedup vs baseline: 1.2863x; 1.1045x over previous
#include <cuda_runtime.h>
#include <cuda_bf16.h>
#include <mma.h>
#include <cstdint>
#include <cstddef>

using namespace nvcuda;

// ---------------------------------------------------------------------------
// 2-layer TF LSTM: B=32, T=512, INSZ=HSZ=1024, G=4096.
// Output: concat(out1[32,512,1024], h1[32,1024], c1[32,1024]) f32.
// R12: mm_kernel rewritten — fused 3-segment K loop, cp.async double
//      buffering, 128x128 CTA tile.  rec/splits unchanged (R11 passing).
// ---------------------------------------------------------------------------

#define BSZ   32
#define TSTEP 512
#define HS    1024
#define GSZ   4096
#define MROWS (BSZ * TSTEP)      // 16384
#define NBLK  128

typedef unsigned long long u64;

// ----------------------------- device scratch ------------------------------
__device__ __align__(16) float g_xproj[(size_t)MROWS * GSZ];
__device__ __align__(16) float g_out0 [(size_t)MROWS * HS];
__device__ __align__(16) float g_hbuf [2 * HS * BSZ];
__device__ __align__(16) __nv_bfloat16 g_ah[(size_t)MROWS * HS];
__device__ __align__(16) __nv_bfloat16 g_al[(size_t)MROWS * HS];
__device__ __align__(16) __nv_bfloat16 g_wh[(size_t)HS * GSZ];
__device__ __align__(16) __nv_bfloat16 g_wl[(size_t)HS * GSZ];
__device__ unsigned g_bar;

// ----------------------------- helpers -------------------------------------
__device__ __forceinline__ u64 pack2(float lo, float hi) {
    u64 r; asm("mov.b64 %0, {%1, %2};" : "=l"(r) : "f"(lo), "f"(hi)); return r;
}
__device__ __forceinline__ void unpack2(u64 v, float& lo, float& hi) {
    asm("mov.b64 {%0, %1}, %2;" : "=f"(lo), "=f"(hi) : "l"(v));
}
__device__ __forceinline__ u64 ffma2(u64 a, u64 b, u64 c) {
    u64 d; asm("fma.rn.f32x2 %0, %1, %2, %3;" : "=l"(d) : "l"(a), "l"(b), "l"(c)); return d;
}
__device__ __forceinline__ float sigf(float x) { return 1.0f / (1.0f + __expf(-x)); }

__device__ __forceinline__ void cpasync16(uint32_t s, const void* g) {
    asm volatile("cp.async.cg.shared.global [%0], [%1], 16;"
                 :: "r"(s), "l"(g) : "memory");
}
#define CP_COMMIT() asm volatile("cp.async.commit_group;" ::: "memory")
#define CP_WAIT(n)  asm volatile("cp.async.wait_group %0;" :: "n"(n) : "memory")

__global__ void init_bar_kernel() { g_bar = 0u; }

// ---------------------------------------------------------------------------
// split_kernel: fp32 -> bf16 hi/lo
// ---------------------------------------------------------------------------
__global__ void __launch_bounds__(256) split_kernel(
    const float* __restrict__ in, __nv_bfloat16* __restrict__ hi,
    __nv_bfloat16* __restrict__ lo)
{
    size_t i = ((size_t)blockIdx.x * 256 + threadIdx.x) * 4;
    float4 v = *(const float4*)(in + i);
    __nv_bfloat16 h0 = __float2bfloat16(v.x);
    __nv_bfloat16 h1 = __float2bfloat16(v.y);
    __nv_bfloat16 h2 = __float2bfloat16(v.z);
    __nv_bfloat16 h3 = __float2bfloat16(v.w);
    __nv_bfloat16 l0 = __float2bfloat16(v.x - __bfloat162float(h0));
    __nv_bfloat16 l1 = __float2bfloat16(v.y - __bfloat162float(h1));
    __nv_bfloat16 l2 = __float2bfloat16(v.z - __bfloat162float(h2));
    __nv_bfloat16 l3 = __float2bfloat16(v.w - __bfloat162float(h3));
    __nv_bfloat162* H = (__nv_bfloat162*)(hi + i);
    __nv_bfloat162* L = (__nv_bfloat162*)(lo + i);
    H[0] = __halves2bfloat162(h0, h1); H[1] = __halves2bfloat162(h2, h3);
    L[0] = __halves2bfloat162(l0, l1); L[1] = __halves2bfloat162(l2, l3);
}

// ---------------------------------------------------------------------------
// mm_kernel: C = Ah@Wh + Al@Wh + Ah@Wl + bias.  CTA 128m x 128n, BK=32,
// 256 thr, 8 warps (4m x 2n), warp tile 32x64 (2x4 wmma frags).
// cp.async double-buffered; 3 segments fused per chunk.
// ---------------------------------------------------------------------------
#define LDA 40     // bf16 elements per A-tile row (32 + 8 pad)
#define LDB 136    // bf16 elements per W-tile row (128 + 8 pad)
#define AT_BYTES (128 * LDA * 2)   // 10240
#define WT_BYTES (32 * LDB * 2)    // 8704
#define STAGE    (2 * AT_BYTES + 2 * WT_BYTES)   // 37888
#define MM_SMEM  (2 * STAGE)                     // 75776

__global__ void __launch_bounds__(256) mm_kernel(
    const __nv_bfloat16* __restrict__ Ah, const __nv_bfloat16* __restrict__ Al,
    const __nv_bfloat16* __restrict__ Bh, const __nv_bfloat16* __restrict__ Bl,
    const float* __restrict__ bias, float* __restrict__ C)
{
    extern __shared__ __align__(16) char smem[];
    __shared__ float biasS[128];

    const int tid = threadIdx.x;
    const int wid = tid >> 5;
    const int wm = wid >> 1, wn = wid & 1;
    const int m0 = blockIdx.y * 128;
    const int n0 = blockIdx.x * 128;

    if (tid < 128) biasS[tid] = bias[n0 + tid];

    uint32_t sbase;
    asm("{ .reg .u64 t; cvta.to.shared.u64 t, %1; cvt.u32.u64 %0, t; }"
        : "=r"(sbase) : "l"(smem));

    // per-thread load coords (8 cp.async of 16B per chunk)
    //   A tiles: f = tid*2+r (r<2): row=f>>2, c16=f&3
    //   W tiles: f = tid*2+r:       row=f>>4, c16=f&15
    const int aR0 = (tid * 2)     >> 2, aC0 = ((tid * 2)     & 3) * 8;
    const int aR1 = (tid * 2 + 1) >> 2, aC1 = ((tid * 2 + 1) & 3) * 8;
    const int wR0 = (tid * 2)     >> 4, wC0 = ((tid * 2)     & 15) * 8;
    const int wR1 = (tid * 2 + 1) >> 4, wC1 = ((tid * 2 + 1) & 15) * 8;

    auto prefetch = [&](int k0, int s) {
        uint32_t st = sbase + s * STAGE;
        uint32_t sAh = st;
        uint32_t sAl = st + AT_BYTES;
        uint32_t sWh = st + 2 * AT_BYTES;
        uint32_t sWl = st + 2 * AT_BYTES + WT_BYTES;
        cpasync16(sAh + (aR0 * LDA + aC0) * 2, Ah + (size_t)(m0 + aR0) * HS + k0 + aC0);
        cpasync16(sAh + (aR1 * LDA + aC1) * 2, Ah + (size_t)(m0 + aR1) * HS + k0 + aC1);
        cpasync16(sAl + (aR0 * LDA + aC0) * 2, Al + (size_t)(m0 + aR0) * HS + k0 + aC0);
        cpasync16(sAl + (aR1 * LDA + aC1) * 2, Al + (size_t)(m0 + aR1) * HS + k0 + aC1);
        cpasync16(sWh + (wR0 * LDB + wC0) * 2, Bh + (size_t)(k0 + wR0) * GSZ + n0 + wC0);
        cpasync16(sWh + (wR1 * LDB + wC1) * 2, Bh + (size_t)(k0 + wR1) * GSZ + n0 + wC1);
        cpasync16(sWl + (wR0 * LDB + wC0) * 2, Bl + (size_t)(k0 + wR0) * GSZ + n0 + wC0);
        cpasync16(sWl + (wR1 * LDB + wC1) * 2, Bl + (size_t)(k0 + wR1) * GSZ + n0 + wC1);
        CP_COMMIT();
    };

    wmma::fragment<wmma::accumulator, 16, 16, 16, float> acc[2][4];
#pragma unroll
    for (int i = 0; i < 2; ++i)
#pragma unroll
        for (int j = 0; j < 4; ++j)
            wmma::fill_fragment(acc[i][j], 0.0f);

    prefetch(0, 0);

#pragma unroll 1
    for (int c = 0; c < 32; ++c) {
        if (c < 31) prefetch((c + 1) * 32, (c + 1) & 1);
        if (c < 31) { CP_WAIT(1); } else { CP_WAIT(0); }
        __syncthreads();

        const char* st = smem + (c & 1) * STAGE;
        const __nv_bfloat16* sAh = (const __nv_bfloat16*)st;
        const __nv_bfloat16* sAl = (const __nv_bfloat16*)(st + AT_BYTES);
        const __nv_bfloat16* sWh = (const __nv_bfloat16*)(st + 2 * AT_BYTES);
        const __nv_bfloat16* sWl = (const __nv_bfloat16*)(st + 2 * AT_BYTES + WT_BYTES);

#pragma unroll
        for (int ks = 0; ks < 2; ++ks) {
            wmma::fragment<wmma::matrix_a, 16, 16, 16, __nv_bfloat16,
                           wmma::row_major> ah[2], al[2];
            wmma::fragment<wmma::matrix_b, 16, 16, 16, __nv_bfloat16,
                           wmma::row_major> wh[4], wl[4];
#pragma unroll
            for (int i = 0; i < 2; ++i) {
                wmma::load_matrix_sync(ah[i],
                    sAh + (size_t)(wm * 32 + i * 16) * LDA + ks * 16, LDA);
                wmma::load_matrix_sync(al[i],
                    sAl + (size_t)(wm * 32 + i * 16) * LDA + ks * 16, LDA);
            }
#pragma unroll
            for (int j = 0; j < 4; ++j) {
                wmma::load_matrix_sync(wh[j],
                    sWh + (size_t)(ks * 16) * LDB + wn * 64 + j * 16, LDB);
                wmma::load_matrix_sync(wl[j],
                    sWl + (size_t)(ks * 16) * LDB + wn * 64 + j * 16, LDB);
            }
#pragma unroll
            for (int i = 0; i < 2; ++i)
#pragma unroll
                for (int j = 0; j < 4; ++j) {
                    wmma::mma_sync(acc[i][j], ah[i], wh[j], acc[i][j]);
                    wmma::mma_sync(acc[i][j], al[i], wh[j], acc[i][j]);
                    wmma::mma_sync(acc[i][j], ah[i], wl[j], acc[i][j]);
                }
        }
        __syncthreads();
    }

    // epilogue through smem (reuse the tile buffers as 128x128 f32)
    float* Csh = (float*)smem;
#pragma unroll
    for (int i = 0; i < 2; ++i)
#pragma unroll
        for (int j = 0; j < 4; ++j)
            wmma::store_matrix_sync(
                Csh + (size_t)(wm * 32 + i * 16) * 128 + wn * 64 + j * 16,
                acc[i][j], 128, wmma::mem_row_major);
    __syncthreads();

#pragma unroll
    for (int r = 0; r < 16; ++r) {
        int f = tid + r * 256;
        int row = f >> 5, cc = (f & 31) * 4;
        float4 v = *(float4*)(Csh + (size_t)row * 128 + cc);
        v.x += biasS[cc + 0]; v.y += biasS[cc + 1];
        v.z += biasS[cc + 2]; v.w += biasS[cc + 3];
        *(float4*)(C + (size_t)(m0 + row) * GSZ + n0 + cc) = v;
    }
}

// ---------------------------------------------------------------------------
// Recurrence (unchanged from R9/R11): persistent, 128 CTAs x 512 threads.
// ---------------------------------------------------------------------------
#define REC_SMEM_FLOATS (32768 + 16384 + 256 + 256 + 32)
#define REC_SMEM_BYTES  (REC_SMEM_FLOATS * 4)

__device__ __forceinline__ void grid_sync(unsigned target)
{
    __syncthreads();
    if (threadIdx.x == 0) {
        asm volatile("red.release.gpu.global.add.u32 [%0], %1;"
                     :: "l"(&g_bar), "r"(1u) : "memory");
        unsigned v;
        do {
            asm volatile("ld.acquire.gpu.global.u32 %0, [%1];"
                         : "=r"(v) : "l"(&g_bar) : "memory");
        } while (v < target);
    }
    __syncthreads();
}

__global__ void __launch_bounds__(512) rec_kernel(
    const float* __restrict__ xproj,
    const float* __restrict__ W,
    const int*   __restrict__ lengths,
    float*       __restrict__ out_h,
    float*       __restrict__ hc_final)
{
    extern __shared__ __align__(16) float sm[];
    float* Wsh   = sm;
    float* zsh   = Wsh + 32768;
    float* csh   = zsh + 16384;
    float* hown  = csh + 256;
    int*   lensh = (int*)(hown + 256);

    const int tid = threadIdx.x;
    const int blk = blockIdx.x;
    const int b   = tid & 31;
    const int w   = tid >> 5;

    for (int i = tid; i < 32768; i += 512) {
        int k = i >> 5, j = i & 31;
        int g = j >> 3, jh = j & 7;
        Wsh[i] = W[(size_t)(HS + k) * GSZ + g * HS + blk * 8 + jh];
    }
    if (tid < 32) lensh[tid] = lengths[tid];
    if (tid < 256) {
        csh[tid] = 0.0f; hown[tid] = 0.0f;
        __stcg(&g_hbuf[blk * 256 + tid], 0.0f);
    }

    unsigned bar_t = NBLK;
    grid_sync(bar_t);

    int cur = 0;
    const ulonglong2* Wsh2 = (const ulonglong2*)Wsh;

    for (int t = 0; t < TSTEP; t++) {
        float xz[4];
        if (tid < 256) {
            int bu = tid >> 3, jh = tid & 7;
            const float* xp =
                xproj + ((size_t)(bu * TSTEP + t)) * GSZ + blk * 8 + jh;
#pragma unroll
            for (int g = 0; g < 4; g++) xz[g] = __ldcg(xp + g * HS);
        }

        u64 acc[16];
#pragma unroll
        for (int i = 0; i < 16; i++) acc[i] = 0ull;

        const float* hsrc = g_hbuf + (size_t)cur * 32768 + w * 16 * 32 + b;
        float hr[2][16];
#pragma unroll
        for (int i = 0; i < 16; i++)
            hr[0][i] = __ldcg(hsrc + i * 32);

#pragma unroll
        for (int q = 0; q < 4; q++) {
            if (q < 3) {
                const float* nsrc = hsrc + (q + 1) * 256 * 32;
#pragma unroll
                for (int i = 0; i < 16; i++)
                    hr[(q + 1) & 1][i] = __ldcg(nsrc + i * 32);
            }

            const ulonglong2* Wr = Wsh2 + (size_t)(q * 256 + w * 16) * 8;
#pragma unroll
            for (int kk = 0; kk < 16; kk++) {
                float hv = hr[q & 1][kk];
                u64 h2 = pack2(hv, hv);
                const ulonglong2* Wk = Wr + kk * 8;
#pragma unroll
                for (int j = 0; j < 8; j++) {
                    ulonglong2 wp = Wk[j];
                    acc[2 * j]     = ffma2(h2, wp.x, acc[2 * j]);
                    acc[2 * j + 1] = ffma2(h2, wp.y, acc[2 * j + 1]);
                }
            }
        }

        {
            float4* z4 = (float4*)zsh;
#pragma unroll
            for (int j = 0; j < 8; j++) {
                int col0 = 4 * j;
                int g = col0 >> 3, jh0 = col0 & 7;
                float a0, a1, a2, a3;
                unpack2(acc[2 * j], a0, a1);
                unpack2(acc[2 * j + 1], a2, a3);
                z4[(w * 1024 + g * 256 + b * 8 + jh0) >> 2] =
                    make_float4(a0, a1, a2, a3);
            }
        }
        __syncthreads();

        const int nxt = cur ^ 1;
        if (tid < 256) {
            int u  = tid;
            int bu = u >> 3, jh = u & 7;
            float zq[4];
#pragma unroll
            for (int g = 0; g < 4; g++) {
                float s = xz[g];
#pragma unroll
                for (int c = 0; c < 16; c++)
                    s += zsh[c * 1024 + g * 256 + u];
                zq[g] = s;
            }
            float cp = csh[u];
            float cn = sigf(zq[2] + 1.0f) * cp + sigf(zq[0]) * tanhf(zq[1]);
            float hn = sigf(zq[3]) * tanhf(cn);
            bool mask = (t < lensh[bu]);
            float hk = mask ? hn : hown[u];
            float ck = mask ? cn : cp;
            csh[u]  = ck;
            hown[u] = hk;
            int kg = blk * 8 + jh;
            out_h[((size_t)bu * TSTEP + t) * HS + kg] = mask ? hn : 0.0f;
            __stcg(&g_hbuf[(size_t)nxt * 32768 + kg * 32 + bu], hk);
            if (hc_final != nullptr && t == TSTEP - 1) {
                hc_final[(size_t)bu * HS + kg]         = hk;
                hc_final[32768 + (size_t)bu * HS + kg] = ck;
            }
        }

        bar_t += NBLK;
        grid_sync(bar_t);
        cur = nxt;
    }
}

// ---------------------------------------------------------------------------
extern "C" void kernel_launch(void* const* d_in, const int* in_sizes, int n_in,
                              void* d_out, int out_size)
{
    const float* x       = (const float*)d_in[0];
    const int*   lengths = (const int*)  d_in[1];
    const float* W0      = (const float*)d_in[2];
    const float* b0      = (const float*)d_in[3];
    const float* W1      = (const float*)d_in[4];
    const float* b1      = (const float*)d_in[5];
    float*       out     = (float*)d_out;

    (void)in_sizes; (void)n_in; (void)out_size;

    cudaFuncSetAttribute(rec_kernel,
                         cudaFuncAttributeMaxDynamicSharedMemorySize,
                         REC_SMEM_BYTES);
    cudaFuncSetAttribute(mm_kernel,
                         cudaFuncAttributeMaxDynamicSharedMemorySize,
                         MM_SMEM);

    float* xproj = nullptr;
    float* out0  = nullptr;
    __nv_bfloat16 *ah, *al, *wh, *wl;
    cudaGetSymbolAddress((void**)&xproj, g_xproj);
    cudaGetSymbolAddress((void**)&out0,  g_out0);
    cudaGetSymbolAddress((void**)&ah, g_ah);
    cudaGetSymbolAddress((void**)&al, g_al);
    cudaGetSymbolAddress((void**)&wh, g_wh);
    cudaGetSymbolAddress((void**)&wl, g_wl);

    dim3 mgrid(GSZ / 128, MROWS / 128);   // (32, 128)

    // Layer 0
    split_kernel<<<(MROWS * HS) / 1024, 256>>>(x, ah, al);
    split_kernel<<<(HS * GSZ) / 1024, 256>>>(W0, wh, wl);
    mm_kernel<<<mgrid, 256, MM_SMEM>>>(ah, al, wh, wl, b0, xproj);
    init_bar_kernel<<<1, 1>>>();
    rec_kernel<<<NBLK, 512, REC_SMEM_BYTES>>>(xproj, W0, lengths, out0, nullptr);

    // Layer 1
    split_kernel<<<(MROWS * HS) / 1024, 256>>>(out0, ah, al);
    split_kernel<<<(HS * GSZ) / 1024, 256>>>(W1, wh, wl);
    mm_kernel<<<mgrid, 256, MM_SMEM>>>(ah, al, wh, wl, b1, xproj);
    init_bar_kernel<<<1, 1>>>();
    rec_kernel<<<NBLK, 512, REC_SMEM_BYTES>>>(xproj, W1, lengths,
                                              out, out + (size_t)MROWS * HS);
}

// round 13
// speedup vs baseline: 1.3978x; 1.0866x over previous
#include <cuda_runtime.h>
#include <cuda_bf16.h>
#include <mma.h>
#include <cstdint>
#include <cstddef>

using namespace nvcuda;

// ---------------------------------------------------------------------------
// 2-layer TF LSTM: B=32, T=512, INSZ=HSZ=1024, G=4096.
// Output: concat(out1[32,512,1024], h1[32,1024], c1[32,1024]) f32.
// R13: recurrence per-step GEMM moved to wmma bf16 split-precision
//      (z^T orientation: A=Wh col_major, B=h row_major, both layout-native);
//      h carried in global bf16 hi/lo, staged via cp.async.  mm = R12.
// ---------------------------------------------------------------------------

#define BSZ   32
#define TSTEP 512
#define HS    1024
#define GSZ   4096
#define MROWS (BSZ * TSTEP)      // 16384
#define NBLK  128

typedef unsigned long long u64;

// ----------------------------- device scratch ------------------------------
__device__ __align__(16) float g_xproj[(size_t)MROWS * GSZ];
__device__ __align__(16) float g_out0 [(size_t)MROWS * HS];
__device__ __align__(16) __nv_bfloat16 g_hbh[2 * HS * BSZ];   // h hi, [buf][k][b]
__device__ __align__(16) __nv_bfloat16 g_hbl[2 * HS * BSZ];   // h lo
__device__ __align__(16) __nv_bfloat16 g_ah[(size_t)MROWS * HS];
__device__ __align__(16) __nv_bfloat16 g_al[(size_t)MROWS * HS];
__device__ __align__(16) __nv_bfloat16 g_wh[(size_t)HS * GSZ];
__device__ __align__(16) __nv_bfloat16 g_wl[(size_t)HS * GSZ];
__device__ unsigned g_bar;

// ----------------------------- helpers -------------------------------------
__device__ __forceinline__ float sigf(float x) { return 1.0f / (1.0f + __expf(-x)); }

__device__ __forceinline__ void cpasync16(uint32_t s, const void* g) {
    asm volatile("cp.async.cg.shared.global [%0], [%1], 16;"
                 :: "r"(s), "l"(g) : "memory");
}
#define CP_COMMIT() asm volatile("cp.async.commit_group;" ::: "memory")
#define CP_WAIT(n)  asm volatile("cp.async.wait_group %0;" :: "n"(n) : "memory")

__device__ __forceinline__ void stg_cg_u16(unsigned short* p, unsigned short v) {
    asm volatile("st.global.cg.u16 [%0], %1;" :: "l"(p), "h"(v) : "memory");
}

__global__ void init_bar_kernel() { g_bar = 0u; }

// ---------------------------------------------------------------------------
// split_kernel: fp32 -> bf16 hi/lo
// ---------------------------------------------------------------------------
__global__ void __launch_bounds__(256) split_kernel(
    const float* __restrict__ in, __nv_bfloat16* __restrict__ hi,
    __nv_bfloat16* __restrict__ lo)
{
    size_t i = ((size_t)blockIdx.x * 256 + threadIdx.x) * 4;
    float4 v = *(const float4*)(in + i);
    __nv_bfloat16 h0 = __float2bfloat16(v.x);
    __nv_bfloat16 h1 = __float2bfloat16(v.y);
    __nv_bfloat16 h2 = __float2bfloat16(v.z);
    __nv_bfloat16 h3 = __float2bfloat16(v.w);
    __nv_bfloat16 l0 = __float2bfloat16(v.x - __bfloat162float(h0));
    __nv_bfloat16 l1 = __float2bfloat16(v.y - __bfloat162float(h1));
    __nv_bfloat16 l2 = __float2bfloat16(v.z - __bfloat162float(h2));
    __nv_bfloat16 l3 = __float2bfloat16(v.w - __bfloat162float(h3));
    __nv_bfloat162* H = (__nv_bfloat162*)(hi + i);
    __nv_bfloat162* L = (__nv_bfloat162*)(lo + i);
    H[0] = __halves2bfloat162(h0, h1); H[1] = __halves2bfloat162(h2, h3);
    L[0] = __halves2bfloat162(l0, l1); L[1] = __halves2bfloat162(l2, l3);
}

// ---------------------------------------------------------------------------
// mm_kernel (R12, unchanged): C = Ah@Wh + Al@Wh + Ah@Wl + bias
// ---------------------------------------------------------------------------
#define LDA 40
#define LDB 136
#define AT_BYTES (128 * LDA * 2)
#define WT_BYTES (32 * LDB * 2)
#define STAGE    (2 * AT_BYTES + 2 * WT_BYTES)
#define MM_SMEM  (2 * STAGE)

__global__ void __launch_bounds__(256) mm_kernel(
    const __nv_bfloat16* __restrict__ Ah, const __nv_bfloat16* __restrict__ Al,
    const __nv_bfloat16* __restrict__ Bh, const __nv_bfloat16* __restrict__ Bl,
    const float* __restrict__ bias, float* __restrict__ C)
{
    extern __shared__ __align__(128) char smem[];
    __shared__ float biasS[128];

    const int tid = threadIdx.x;
    const int wid = tid >> 5;
    const int wm = wid >> 1, wn = wid & 1;
    const int m0 = blockIdx.y * 128;
    const int n0 = blockIdx.x * 128;

    if (tid < 128) biasS[tid] = bias[n0 + tid];

    uint32_t sbase;
    asm("{ .reg .u64 t; cvta.to.shared.u64 t, %1; cvt.u32.u64 %0, t; }"
        : "=r"(sbase) : "l"(smem));

    const int aR0 = (tid * 2)     >> 2, aC0 = ((tid * 2)     & 3) * 8;
    const int aR1 = (tid * 2 + 1) >> 2, aC1 = ((tid * 2 + 1) & 3) * 8;
    const int wR0 = (tid * 2)     >> 4, wC0 = ((tid * 2)     & 15) * 8;
    const int wR1 = (tid * 2 + 1) >> 4, wC1 = ((tid * 2 + 1) & 15) * 8;

    auto prefetch = [&](int k0, int s) {
        uint32_t st = sbase + s * STAGE;
        uint32_t sAh = st;
        uint32_t sAl = st + AT_BYTES;
        uint32_t sWh = st + 2 * AT_BYTES;
        uint32_t sWl = st + 2 * AT_BYTES + WT_BYTES;
        cpasync16(sAh + (aR0 * LDA + aC0) * 2, Ah + (size_t)(m0 + aR0) * HS + k0 + aC0);
        cpasync16(sAh + (aR1 * LDA + aC1) * 2, Ah + (size_t)(m0 + aR1) * HS + k0 + aC1);
        cpasync16(sAl + (aR0 * LDA + aC0) * 2, Al + (size_t)(m0 + aR0) * HS + k0 + aC0);
        cpasync16(sAl + (aR1 * LDA + aC1) * 2, Al + (size_t)(m0 + aR1) * HS + k0 + aC1);
        cpasync16(sWh + (wR0 * LDB + wC0) * 2, Bh + (size_t)(k0 + wR0) * GSZ + n0 + wC0);
        cpasync16(sWh + (wR1 * LDB + wC1) * 2, Bh + (size_t)(k0 + wR1) * GSZ + n0 + wC1);
        cpasync16(sWl + (wR0 * LDB + wC0) * 2, Bl + (size_t)(k0 + wR0) * GSZ + n0 + wC0);
        cpasync16(sWl + (wR1 * LDB + wC1) * 2, Bl + (size_t)(k0 + wR1) * GSZ + n0 + wC1);
        CP_COMMIT();
    };

    wmma::fragment<wmma::accumulator, 16, 16, 16, float> acc[2][4];
#pragma unroll
    for (int i = 0; i < 2; ++i)
#pragma unroll
        for (int j = 0; j < 4; ++j)
            wmma::fill_fragment(acc[i][j], 0.0f);

    prefetch(0, 0);

#pragma unroll 1
    for (int c = 0; c < 32; ++c) {
        if (c < 31) prefetch((c + 1) * 32, (c + 1) & 1);
        if (c < 31) { CP_WAIT(1); } else { CP_WAIT(0); }
        __syncthreads();

        const char* st = smem + (c & 1) * STAGE;
        const __nv_bfloat16* sAh = (const __nv_bfloat16*)st;
        const __nv_bfloat16* sAl = (const __nv_bfloat16*)(st + AT_BYTES);
        const __nv_bfloat16* sWh = (const __nv_bfloat16*)(st + 2 * AT_BYTES);
        const __nv_bfloat16* sWl = (const __nv_bfloat16*)(st + 2 * AT_BYTES + WT_BYTES);

#pragma unroll
        for (int ks = 0; ks < 2; ++ks) {
            wmma::fragment<wmma::matrix_a, 16, 16, 16, __nv_bfloat16,
                           wmma::row_major> ah[2], al[2];
            wmma::fragment<wmma::matrix_b, 16, 16, 16, __nv_bfloat16,
                           wmma::row_major> wh[4], wl[4];
#pragma unroll
            for (int i = 0; i < 2; ++i) {
                wmma::load_matrix_sync(ah[i],
                    sAh + (size_t)(wm * 32 + i * 16) * LDA + ks * 16, LDA);
                wmma::load_matrix_sync(al[i],
                    sAl + (size_t)(wm * 32 + i * 16) * LDA + ks * 16, LDA);
            }
#pragma unroll
            for (int j = 0; j < 4; ++j) {
                wmma::load_matrix_sync(wh[j],
                    sWh + (size_t)(ks * 16) * LDB + wn * 64 + j * 16, LDB);
                wmma::load_matrix_sync(wl[j],
                    sWl + (size_t)(ks * 16) * LDB + wn * 64 + j * 16, LDB);
            }
#pragma unroll
            for (int i = 0; i < 2; ++i)
#pragma unroll
                for (int j = 0; j < 4; ++j) {
                    wmma::mma_sync(acc[i][j], ah[i], wh[j], acc[i][j]);
                    wmma::mma_sync(acc[i][j], al[i], wh[j], acc[i][j]);
                    wmma::mma_sync(acc[i][j], ah[i], wl[j], acc[i][j]);
                }
        }
        __syncthreads();
    }

    float* Csh = (float*)smem;
#pragma unroll
    for (int i = 0; i < 2; ++i)
#pragma unroll
        for (int j = 0; j < 4; ++j)
            wmma::store_matrix_sync(
                Csh + (size_t)(wm * 32 + i * 16) * 128 + wn * 64 + j * 16,
                acc[i][j], 128, wmma::mem_row_major);
    __syncthreads();

#pragma unroll
    for (int r = 0; r < 16; ++r) {
        int f = tid + r * 256;
        int row = f >> 5, cc = (f & 31) * 4;
        float4 v = *(float4*)(Csh + (size_t)row * 128 + cc);
        v.x += biasS[cc + 0]; v.y += biasS[cc + 1];
        v.z += biasS[cc + 2]; v.w += biasS[cc + 3];
        *(float4*)(C + (size_t)(m0 + row) * GSZ + n0 + cc) = v;
    }
}

// ---------------------------------------------------------------------------
// Recurrence: persistent, 128 CTAs x 256 threads (8 warps).
// z^T[j=gatecol][b] = Wh^T @ h via wmma m16n16k16 bf16 split (3-term).
//   A = Wh slice, col_major from smem [k][32j], ldm=32
//   B = h, row_major from staged smem [k][32b], ldb=32
// h lives in global bf16 hi/lo ping-pong; staged per 256-k chunk (cp.async,
// 2 buffers, 1 sync/phase).  Warp w: k-tiles {w*2, w*2+1} of each chunk;
// acc 2x2 frags; 8 warp-partials reduced in the cell phase.
// ---------------------------------------------------------------------------
#define RW_HH   0                        // Wh hi  [1024][32] bf16, 65536 B
#define RW_HL   65536                    // Wh lo
#define R_HST   131072                   // 2 bufs x (hi 16384 + lo 16384)
#define R_ZSH   196608                   // 8 x [32j][32b] f32, 32768 B
#define R_CSH   229376                   // 256 f32
#define R_HOWN  230400                   // 256 f32
#define R_LEN   231424                   // 32 i32
#define REC_SMEM_BYTES 231552

__device__ __forceinline__ void grid_sync(unsigned target)
{
    __syncthreads();
    if (threadIdx.x == 0) {
        asm volatile("red.release.gpu.global.add.u32 [%0], %1;"
                     :: "l"(&g_bar), "r"(1u) : "memory");
        unsigned v;
        do {
            asm volatile("ld.acquire.gpu.global.u32 %0, [%1];"
                         : "=r"(v) : "l"(&g_bar) : "memory");
        } while (v < target);
    }
    __syncthreads();
}

__global__ void __launch_bounds__(256) rec_kernel(
    const float* __restrict__ xproj,
    const float* __restrict__ W,
    const int*   __restrict__ lengths,
    float*       __restrict__ out_h,
    float*       __restrict__ hc_final)
{
    extern __shared__ __align__(128) char sm[];
    __nv_bfloat16* Whh = (__nv_bfloat16*)(sm + RW_HH);
    __nv_bfloat16* Whl = (__nv_bfloat16*)(sm + RW_HL);
    float* zsh  = (float*)(sm + R_ZSH);
    float* csh  = (float*)(sm + R_CSH);
    float* hown = (float*)(sm + R_HOWN);
    int*   lensh = (int*)(sm + R_LEN);

    const int tid = threadIdx.x;
    const int blk = blockIdx.x;
    const int w   = tid >> 5;

    uint32_t sbase;
    asm("{ .reg .u64 t; cvta.to.shared.u64 t, %1; cvt.u32.u64 %0, t; }"
        : "=r"(sbase) : "l"(sm));

    // Wh slice -> smem bf16 hi/lo: Whh[k*32 + j], j=g*8+jh (A col_major)
    for (int i = tid; i < 32768; i += 256) {
        int k = i >> 5, j = i & 31;
        int g = j >> 3, jh = j & 7;
        float v = W[(size_t)(HS + k) * GSZ + g * HS + blk * 8 + jh];
        __nv_bfloat16 hi = __float2bfloat16(v);
        __nv_bfloat16 lo = __float2bfloat16(v - __bfloat162float(hi));
        Whh[i] = hi; Whl[i] = lo;
    }
    if (tid < 32) lensh[tid] = lengths[tid];
    csh[tid] = 0.0f; hown[tid] = 0.0f;
    {   // zero h(0) bf16 slice (buffer 0)
        int k = blk * 8 + (tid >> 5), b = tid & 31;
        stg_cg_u16((unsigned short*)g_hbh + (size_t)k * 32 + b, 0);
        stg_cg_u16((unsigned short*)g_hbl + (size_t)k * 32 + b, 0);
    }

    unsigned bar_t = NBLK;
    grid_sync(bar_t);

    int cur = 0;

    auto stage = [&](int c, int buf, int curb) {
        uint32_t dhi = sbase + R_HST + buf * 32768;
        uint32_t dlo = dhi + 16384;
        const char* sh = (const char*)(g_hbh + (size_t)curb * 32768 + c * 256 * 32);
        const char* sl = (const char*)(g_hbl + (size_t)curb * 32768 + c * 256 * 32);
#pragma unroll
        for (int r = 0; r < 4; ++r) {
            int u = tid + r * 256;            // 0..1023 16B units
            cpasync16(dhi + u * 16, sh + u * 16);
            cpasync16(dlo + u * 16, sl + u * 16);
        }
        CP_COMMIT();
    };

    for (int t = 0; t < TSTEP; t++) {
        // hoisted xproj loads (consumed in cell phase)
        float xz[4];
        {
            int bu = tid >> 3, jh = tid & 7;
            const float* xp =
                xproj + ((size_t)(bu * TSTEP + t)) * GSZ + blk * 8 + jh;
#pragma unroll
            for (int g = 0; g < 4; g++) xz[g] = __ldcg(xp + g * HS);
        }

        stage(0, 0, cur);

        wmma::fragment<wmma::accumulator, 16, 16, 16, float> acc[2][2];
#pragma unroll
        for (int i = 0; i < 2; ++i)
#pragma unroll
            for (int j = 0; j < 2; ++j)
                wmma::fill_fragment(acc[i][j], 0.0f);

#pragma unroll
        for (int c = 0; c < 4; ++c) {
            CP_WAIT(0);
            __syncthreads();
            if (c < 3) stage(c + 1, (c + 1) & 1, cur);

            const char* hb = sm + R_HST + (c & 1) * 32768;
            const __nv_bfloat16* Hh = (const __nv_bfloat16*)hb;
            const __nv_bfloat16* Hl = (const __nv_bfloat16*)(hb + 16384);

#pragma unroll
            for (int kk = 0; kk < 2; ++kk) {
                const int kt = w * 2 + kk;         // k-tile within chunk
                const int kg = c * 256 + kt * 16;  // global k
                wmma::fragment<wmma::matrix_a, 16, 16, 16, __nv_bfloat16,
                               wmma::col_major> fAh[2], fAl[2];
                wmma::fragment<wmma::matrix_b, 16, 16, 16, __nv_bfloat16,
                               wmma::row_major> fBh[2], fBl[2];
#pragma unroll
                for (int mt = 0; mt < 2; ++mt) {
                    wmma::load_matrix_sync(fAh[mt], Whh + (size_t)kg * 32 + mt * 16, 32);
                    wmma::load_matrix_sync(fAl[mt], Whl + (size_t)kg * 32 + mt * 16, 32);
                }
#pragma unroll
                for (int nt = 0; nt < 2; ++nt) {
                    wmma::load_matrix_sync(fBh[nt], Hh + (size_t)kt * 512 + nt * 16, 32);
                    wmma::load_matrix_sync(fBl[nt], Hl + (size_t)kt * 512 + nt * 16, 32);
                }
#pragma unroll
                for (int mt = 0; mt < 2; ++mt)
#pragma unroll
                    for (int nt = 0; nt < 2; ++nt) {
                        wmma::mma_sync(acc[mt][nt], fAh[mt], fBh[nt], acc[mt][nt]);
                        wmma::mma_sync(acc[mt][nt], fAl[mt], fBh[nt], acc[mt][nt]);
                        wmma::mma_sync(acc[mt][nt], fAh[mt], fBl[nt], acc[mt][nt]);
                    }
            }
        }

        // store warp partials: zsh[w][j][b]
#pragma unroll
        for (int mt = 0; mt < 2; ++mt)
#pragma unroll
            for (int nt = 0; nt < 2; ++nt)
                wmma::store_matrix_sync(
                    zsh + (size_t)w * 1024 + mt * 512 + nt * 16,
                    acc[mt][nt], 32, wmma::mem_row_major);
        __syncthreads();

        // cell update: 256 units, one per thread
        const int nxt = cur ^ 1;
        {
            int u  = tid;
            int bu = u >> 3, jh = u & 7;
            float zq[4];
#pragma unroll
            for (int g = 0; g < 4; g++) {
                float s = xz[g];
                int off = (g * 8 + jh) * 32 + bu;
#pragma unroll
                for (int ww = 0; ww < 8; ww++)
                    s += zsh[ww * 1024 + off];
                zq[g] = s;
            }
            float cp = csh[u];
            float cn = sigf(zq[2] + 1.0f) * cp + sigf(zq[0]) * tanhf(zq[1]);
            float hn = sigf(zq[3]) * tanhf(cn);
            bool mask = (t < lensh[bu]);
            float hk = mask ? hn : hown[u];
            float ck = mask ? cn : cp;
            csh[u]  = ck;
            hown[u] = hk;
            int kg = blk * 8 + jh;
            out_h[((size_t)bu * TSTEP + t) * HS + kg] = mask ? hn : 0.0f;
            __nv_bfloat16 hhi = __float2bfloat16(hk);
            __nv_bfloat16 hlo = __float2bfloat16(hk - __bfloat162float(hhi));
            size_t hidx = (size_t)nxt * 32768 + (size_t)kg * 32 + bu;
            stg_cg_u16((unsigned short*)g_hbh + hidx, *(unsigned short*)&hhi);
            stg_cg_u16((unsigned short*)g_hbl + hidx, *(unsigned short*)&hlo);
            if (hc_final != nullptr && t == TSTEP - 1) {
                hc_final[(size_t)bu * HS + kg]         = hk;
                hc_final[32768 + (size_t)bu * HS + kg] = ck;
            }
        }

        bar_t += NBLK;
        grid_sync(bar_t);
        cur = nxt;
    }
}

// ---------------------------------------------------------------------------
extern "C" void kernel_launch(void* const* d_in, const int* in_sizes, int n_in,
                              void* d_out, int out_size)
{
    const float* x       = (const float*)d_in[0];
    const int*   lengths = (const int*)  d_in[1];
    const float* W0      = (const float*)d_in[2];
    const float* b0      = (const float*)d_in[3];
    const float* W1      = (const float*)d_in[4];
    const float* b1      = (const float*)d_in[5];
    float*       out     = (float*)d_out;

    (void)in_sizes; (void)n_in; (void)out_size;

    cudaFuncSetAttribute(rec_kernel,
                         cudaFuncAttributeMaxDynamicSharedMemorySize,
                         REC_SMEM_BYTES);
    cudaFuncSetAttribute(mm_kernel,
                         cudaFuncAttributeMaxDynamicSharedMemorySize,
                         MM_SMEM);

    float* xproj = nullptr;
    float* out0  = nullptr;
    __nv_bfloat16 *ah, *al, *wh, *wl;
    cudaGetSymbolAddress((void**)&xproj, g_xproj);
    cudaGetSymbolAddress((void**)&out0,  g_out0);
    cudaGetSymbolAddress((void**)&ah, g_ah);
    cudaGetSymbolAddress((void**)&al, g_al);
    cudaGetSymbolAddress((void**)&wh, g_wh);
    cudaGetSymbolAddress((void**)&wl, g_wl);

    dim3 mgrid(GSZ / 128, MROWS / 128);   // (32, 128)

    // Layer 0
    split_kernel<<<(MROWS * HS) / 1024, 256>>>(x, ah, al);
    split_kernel<<<(HS * GSZ) / 1024, 256>>>(W0, wh, wl);
    mm_kernel<<<mgrid, 256, MM_SMEM>>>(ah, al, wh, wl, b0, xproj);
    init_bar_kernel<<<1, 1>>>();
    rec_kernel<<<NBLK, 256, REC_SMEM_BYTES>>>(xproj, W0, lengths, out0, nullptr);

    // Layer 1
    split_kernel<<<(MROWS * HS) / 1024, 256>>>(out0, ah, al);
    split_kernel<<<(HS * GSZ) / 1024, 256>>>(W1, wh, wl);
    mm_kernel<<<mgrid, 256, MM_SMEM>>>(ah, al, wh, wl, b1, xproj);
    init_bar_kernel<<<1, 1>>>();
    rec_kernel<<<NBLK, 256, REC_SMEM_BYTES>>>(xproj, W1, lengths,
                                              out, out + (size_t)MROWS * HS);
}

// round 14
// speedup vs baseline: 1.7201x; 1.2306x over previous
#include <cuda_runtime.h>
#include <cuda_bf16.h>
#include <mma.h>
#include <cstdint>
#include <cstddef>

using namespace nvcuda;

// ---------------------------------------------------------------------------
// 2-layer TF LSTM: B=32, T=512, INSZ=HSZ=1024, G=4096.
// Output: concat(out1[32,512,1024], h1[32,1024], c1[32,1024]) f32.
// R14: rec — W wmma fragments preloaded into registers (loop-invariant);
//      warp-local cp.async h staging (no CTA staging syncs; 3 bars/step).
//      mm/splits = R12/R13 (passing).
// ---------------------------------------------------------------------------

#define BSZ   32
#define TSTEP 512
#define HS    1024
#define GSZ   4096
#define MROWS (BSZ * TSTEP)      // 16384
#define NBLK  128

typedef unsigned long long u64;

// ----------------------------- device scratch ------------------------------
__device__ __align__(16) float g_xproj[(size_t)MROWS * GSZ];
__device__ __align__(16) float g_out0 [(size_t)MROWS * HS];
__device__ __align__(16) __nv_bfloat16 g_hbh[2 * HS * BSZ];   // h hi, [buf][k][b]
__device__ __align__(16) __nv_bfloat16 g_hbl[2 * HS * BSZ];   // h lo
__device__ __align__(16) __nv_bfloat16 g_ah[(size_t)MROWS * HS];
__device__ __align__(16) __nv_bfloat16 g_al[(size_t)MROWS * HS];
__device__ __align__(16) __nv_bfloat16 g_wh[(size_t)HS * GSZ];
__device__ __align__(16) __nv_bfloat16 g_wl[(size_t)HS * GSZ];
__device__ unsigned g_bar;

// ----------------------------- helpers -------------------------------------
__device__ __forceinline__ float sigf(float x) { return 1.0f / (1.0f + __expf(-x)); }

__device__ __forceinline__ void cpasync16(uint32_t s, const void* g) {
    asm volatile("cp.async.cg.shared.global [%0], [%1], 16;"
                 :: "r"(s), "l"(g) : "memory");
}
#define CP_COMMIT() asm volatile("cp.async.commit_group;" ::: "memory")
#define CP_WAIT(n)  asm volatile("cp.async.wait_group %0;" :: "n"(n) : "memory")

__device__ __forceinline__ void stg_cg_u16(unsigned short* p, unsigned short v) {
    asm volatile("st.global.cg.u16 [%0], %1;" :: "l"(p), "h"(v) : "memory");
}

__global__ void init_bar_kernel() { g_bar = 0u; }

// ---------------------------------------------------------------------------
// split_kernel: fp32 -> bf16 hi/lo
// ---------------------------------------------------------------------------
__global__ void __launch_bounds__(256) split_kernel(
    const float* __restrict__ in, __nv_bfloat16* __restrict__ hi,
    __nv_bfloat16* __restrict__ lo)
{
    size_t i = ((size_t)blockIdx.x * 256 + threadIdx.x) * 4;
    float4 v = *(const float4*)(in + i);
    __nv_bfloat16 h0 = __float2bfloat16(v.x);
    __nv_bfloat16 h1 = __float2bfloat16(v.y);
    __nv_bfloat16 h2 = __float2bfloat16(v.z);
    __nv_bfloat16 h3 = __float2bfloat16(v.w);
    __nv_bfloat16 l0 = __float2bfloat16(v.x - __bfloat162float(h0));
    __nv_bfloat16 l1 = __float2bfloat16(v.y - __bfloat162float(h1));
    __nv_bfloat16 l2 = __float2bfloat16(v.z - __bfloat162float(h2));
    __nv_bfloat16 l3 = __float2bfloat16(v.w - __bfloat162float(h3));
    __nv_bfloat162* H = (__nv_bfloat162*)(hi + i);
    __nv_bfloat162* L = (__nv_bfloat162*)(lo + i);
    H[0] = __halves2bfloat162(h0, h1); H[1] = __halves2bfloat162(h2, h3);
    L[0] = __halves2bfloat162(l0, l1); L[1] = __halves2bfloat162(l2, l3);
}

// ---------------------------------------------------------------------------
// mm_kernel (R12, unchanged): C = Ah@Wh + Al@Wh + Ah@Wl + bias
// ---------------------------------------------------------------------------
#define LDA 40
#define LDB 136
#define AT_BYTES (128 * LDA * 2)
#define WT_BYTES (32 * LDB * 2)
#define STAGE    (2 * AT_BYTES + 2 * WT_BYTES)
#define MM_SMEM  (2 * STAGE)

__global__ void __launch_bounds__(256) mm_kernel(
    const __nv_bfloat16* __restrict__ Ah, const __nv_bfloat16* __restrict__ Al,
    const __nv_bfloat16* __restrict__ Bh, const __nv_bfloat16* __restrict__ Bl,
    const float* __restrict__ bias, float* __restrict__ C)
{
    extern __shared__ __align__(128) char smem[];
    __shared__ float biasS[128];

    const int tid = threadIdx.x;
    const int wid = tid >> 5;
    const int wm = wid >> 1, wn = wid & 1;
    const int m0 = blockIdx.y * 128;
    const int n0 = blockIdx.x * 128;

    if (tid < 128) biasS[tid] = bias[n0 + tid];

    uint32_t sbase;
    asm("{ .reg .u64 t; cvta.to.shared.u64 t, %1; cvt.u32.u64 %0, t; }"
        : "=r"(sbase) : "l"(smem));

    const int aR0 = (tid * 2)     >> 2, aC0 = ((tid * 2)     & 3) * 8;
    const int aR1 = (tid * 2 + 1) >> 2, aC1 = ((tid * 2 + 1) & 3) * 8;
    const int wR0 = (tid * 2)     >> 4, wC0 = ((tid * 2)     & 15) * 8;
    const int wR1 = (tid * 2 + 1) >> 4, wC1 = ((tid * 2 + 1) & 15) * 8;

    auto prefetch = [&](int k0, int s) {
        uint32_t st = sbase + s * STAGE;
        uint32_t sAh = st;
        uint32_t sAl = st + AT_BYTES;
        uint32_t sWh = st + 2 * AT_BYTES;
        uint32_t sWl = st + 2 * AT_BYTES + WT_BYTES;
        cpasync16(sAh + (aR0 * LDA + aC0) * 2, Ah + (size_t)(m0 + aR0) * HS + k0 + aC0);
        cpasync16(sAh + (aR1 * LDA + aC1) * 2, Ah + (size_t)(m0 + aR1) * HS + k0 + aC1);
        cpasync16(sAl + (aR0 * LDA + aC0) * 2, Al + (size_t)(m0 + aR0) * HS + k0 + aC0);
        cpasync16(sAl + (aR1 * LDA + aC1) * 2, Al + (size_t)(m0 + aR1) * HS + k0 + aC1);
        cpasync16(sWh + (wR0 * LDB + wC0) * 2, Bh + (size_t)(k0 + wR0) * GSZ + n0 + wC0);
        cpasync16(sWh + (wR1 * LDB + wC1) * 2, Bh + (size_t)(k0 + wR1) * GSZ + n0 + wC1);
        cpasync16(sWl + (wR0 * LDB + wC0) * 2, Bl + (size_t)(k0 + wR0) * GSZ + n0 + wC0);
        cpasync16(sWl + (wR1 * LDB + wC1) * 2, Bl + (size_t)(k0 + wR1) * GSZ + n0 + wC1);
        CP_COMMIT();
    };

    wmma::fragment<wmma::accumulator, 16, 16, 16, float> acc[2][4];
#pragma unroll
    for (int i = 0; i < 2; ++i)
#pragma unroll
        for (int j = 0; j < 4; ++j)
            wmma::fill_fragment(acc[i][j], 0.0f);

    prefetch(0, 0);

#pragma unroll 1
    for (int c = 0; c < 32; ++c) {
        if (c < 31) prefetch((c + 1) * 32, (c + 1) & 1);
        if (c < 31) { CP_WAIT(1); } else { CP_WAIT(0); }
        __syncthreads();

        const char* st = smem + (c & 1) * STAGE;
        const __nv_bfloat16* sAh = (const __nv_bfloat16*)st;
        const __nv_bfloat16* sAl = (const __nv_bfloat16*)(st + AT_BYTES);
        const __nv_bfloat16* sWh = (const __nv_bfloat16*)(st + 2 * AT_BYTES);
        const __nv_bfloat16* sWl = (const __nv_bfloat16*)(st + 2 * AT_BYTES + WT_BYTES);

#pragma unroll
        for (int ks = 0; ks < 2; ++ks) {
            wmma::fragment<wmma::matrix_a, 16, 16, 16, __nv_bfloat16,
                           wmma::row_major> ah[2], al[2];
            wmma::fragment<wmma::matrix_b, 16, 16, 16, __nv_bfloat16,
                           wmma::row_major> wh[4], wl[4];
#pragma unroll
            for (int i = 0; i < 2; ++i) {
                wmma::load_matrix_sync(ah[i],
                    sAh + (size_t)(wm * 32 + i * 16) * LDA + ks * 16, LDA);
                wmma::load_matrix_sync(al[i],
                    sAl + (size_t)(wm * 32 + i * 16) * LDA + ks * 16, LDA);
            }
#pragma unroll
            for (int j = 0; j < 4; ++j) {
                wmma::load_matrix_sync(wh[j],
                    sWh + (size_t)(ks * 16) * LDB + wn * 64 + j * 16, LDB);
                wmma::load_matrix_sync(wl[j],
                    sWl + (size_t)(ks * 16) * LDB + wn * 64 + j * 16, LDB);
            }
#pragma unroll
            for (int i = 0; i < 2; ++i)
#pragma unroll
                for (int j = 0; j < 4; ++j) {
                    wmma::mma_sync(acc[i][j], ah[i], wh[j], acc[i][j]);
                    wmma::mma_sync(acc[i][j], al[i], wh[j], acc[i][j]);
                    wmma::mma_sync(acc[i][j], ah[i], wl[j], acc[i][j]);
                }
        }
        __syncthreads();
    }

    float* Csh = (float*)smem;
#pragma unroll
    for (int i = 0; i < 2; ++i)
#pragma unroll
        for (int j = 0; j < 4; ++j)
            wmma::store_matrix_sync(
                Csh + (size_t)(wm * 32 + i * 16) * 128 + wn * 64 + j * 16,
                acc[i][j], 128, wmma::mem_row_major);
    __syncthreads();

#pragma unroll
    for (int r = 0; r < 16; ++r) {
        int f = tid + r * 256;
        int row = f >> 5, cc = (f & 31) * 4;
        float4 v = *(float4*)(Csh + (size_t)row * 128 + cc);
        v.x += biasS[cc + 0]; v.y += biasS[cc + 1];
        v.z += biasS[cc + 2]; v.w += biasS[cc + 3];
        *(float4*)(C + (size_t)(m0 + row) * GSZ + n0 + cc) = v;
    }
}

// ---------------------------------------------------------------------------
// Recurrence: persistent, 128 CTAs x 256 threads (8 warps).
// z^T[j][b] = Wh^T @ h, wmma bf16 3-term split.  W A-fragments preloaded in
// REGISTERS (loop-invariant).  Warp w owns k in [w*128, w*128+128): stages
// its own h (8 tiles x (hi 1KB + lo 1KB)) via per-tile cp.async groups,
// wait_group + syncwarp per tile — no CTA-wide staging syncs.
// Per-step bars: grid_sync(2) + partials(1) = 3.
// ---------------------------------------------------------------------------
#define R_HST   0                        // 8 warps x 16384 B staging
#define R_ZSH   131072                   // 8 x [32j][32b] f32, 32768 B
#define R_CSH   163840                   // 256 f32
#define R_HOWN  164864                   // 256 f32
#define R_LEN   165888                   // 32 i32
#define REC_SMEM_BYTES 166016

__device__ __forceinline__ void grid_sync(unsigned target)
{
    __syncthreads();
    if (threadIdx.x == 0) {
        asm volatile("red.release.gpu.global.add.u32 [%0], %1;"
                     :: "l"(&g_bar), "r"(1u) : "memory");
        unsigned v;
        do {
            asm volatile("ld.acquire.gpu.global.u32 %0, [%1];"
                         : "=r"(v) : "l"(&g_bar) : "memory");
        } while (v < target);
    }
    __syncthreads();
}

__global__ void __launch_bounds__(256) rec_kernel(
    const float* __restrict__ xproj,
    const float* __restrict__ W,
    const int*   __restrict__ lengths,
    float*       __restrict__ out_h,
    float*       __restrict__ hc_final)
{
    extern __shared__ __align__(128) char sm[];
    float* zsh   = (float*)(sm + R_ZSH);
    float* csh   = (float*)(sm + R_CSH);
    float* hown  = (float*)(sm + R_HOWN);
    int*   lensh = (int*)(sm + R_LEN);

    const int tid  = threadIdx.x;
    const int blk  = blockIdx.x;
    const int w    = tid >> 5;
    const int lane = tid & 31;

    uint32_t sbase;
    asm("{ .reg .u64 t; cvta.to.shared.u64 t, %1; cvt.u32.u64 %0, t; }"
        : "=r"(sbase) : "l"(sm));

    // ---- preload W A-fragments into registers (col_major, ldm=32) ----
    wmma::fragment<wmma::matrix_a, 16, 16, 16, __nv_bfloat16,
                   wmma::col_major> fAh[8][2], fAl[8][2];
    {
        __nv_bfloat16* Wtmp = (__nv_bfloat16*)sm;   // 64KB scratch in staging
        for (int i = tid; i < 32768; i += 256) {
            int k = i >> 5, j = i & 31;
            int g = j >> 3, jh = j & 7;
            float v = W[(size_t)(HS + k) * GSZ + g * HS + blk * 8 + jh];
            Wtmp[i] = __float2bfloat16(v);
        }
        __syncthreads();
#pragma unroll
        for (int t = 0; t < 8; ++t)
#pragma unroll
            for (int mt = 0; mt < 2; ++mt)
                wmma::load_matrix_sync(fAh[t][mt],
                    Wtmp + (size_t)(w * 128 + t * 16) * 32 + mt * 16, 32);
        __syncthreads();
        for (int i = tid; i < 32768; i += 256) {
            int k = i >> 5, j = i & 31;
            int g = j >> 3, jh = j & 7;
            float v = W[(size_t)(HS + k) * GSZ + g * HS + blk * 8 + jh];
            __nv_bfloat16 hi = __float2bfloat16(v);
            Wtmp[i] = __float2bfloat16(v - __bfloat162float(hi));
        }
        __syncthreads();
#pragma unroll
        for (int t = 0; t < 8; ++t)
#pragma unroll
            for (int mt = 0; mt < 2; ++mt)
                wmma::load_matrix_sync(fAl[t][mt],
                    Wtmp + (size_t)(w * 128 + t * 16) * 32 + mt * 16, 32);
        __syncthreads();
    }

    if (tid < 32) lensh[tid] = lengths[tid];
    csh[tid] = 0.0f; hown[tid] = 0.0f;
    {   // zero h(0) bf16 slice (buffer 0)
        int k = blk * 8 + w, b = lane;
        stg_cg_u16((unsigned short*)g_hbh + (size_t)k * 32 + b, 0);
        stg_cg_u16((unsigned short*)g_hbl + (size_t)k * 32 + b, 0);
    }

    unsigned bar_t = NBLK;
    grid_sync(bar_t);

    int cur = 0;
    const uint32_t wst = sbase + R_HST + w * 16384;

    for (int t = 0; t < TSTEP; t++) {
        // hoisted xproj loads (consumed in cell phase)
        float xz[4];
        {
            int bu = tid >> 3, jh = tid & 7;
            const float* xp =
                xproj + ((size_t)(bu * TSTEP + t)) * GSZ + blk * 8 + jh;
#pragma unroll
            for (int g = 0; g < 4; g++) xz[g] = __ldcg(xp + g * HS);
        }

        // issue warp-local staging: 8 tiles, one commit group each
        const char* srcH = (const char*)(g_hbh + (size_t)cur * 32768 + (size_t)w * 128 * 32);
        const char* srcL = (const char*)(g_hbl + (size_t)cur * 32768 + (size_t)w * 128 * 32);
#pragma unroll
        for (int tt = 0; tt < 8; ++tt) {
            int o = lane * 32;   // 2x16B per lane
            cpasync16(wst + tt * 2048 + o,           srcH + tt * 1024 + o);
            cpasync16(wst + tt * 2048 + o + 16,      srcH + tt * 1024 + o + 16);
            cpasync16(wst + tt * 2048 + 1024 + o,    srcL + tt * 1024 + o);
            cpasync16(wst + tt * 2048 + 1024 + o + 16, srcL + tt * 1024 + o + 16);
            CP_COMMIT();
        }

        wmma::fragment<wmma::accumulator, 16, 16, 16, float> acc[2][2];
#pragma unroll
        for (int i = 0; i < 2; ++i)
#pragma unroll
            for (int j = 0; j < 2; ++j)
                wmma::fill_fragment(acc[i][j], 0.0f);

#pragma unroll
        for (int tt = 0; tt < 8; ++tt) {
            switch (tt) {
                case 0: CP_WAIT(7); break;
                case 1: CP_WAIT(6); break;
                case 2: CP_WAIT(5); break;
                case 3: CP_WAIT(4); break;
                case 4: CP_WAIT(3); break;
                case 5: CP_WAIT(2); break;
                case 6: CP_WAIT(1); break;
                default: CP_WAIT(0); break;
            }
            __syncwarp();

            const __nv_bfloat16* Hh =
                (const __nv_bfloat16*)(sm + R_HST + w * 16384 + tt * 2048);
            const __nv_bfloat16* Hl =
                (const __nv_bfloat16*)(sm + R_HST + w * 16384 + tt * 2048 + 1024);

            wmma::fragment<wmma::matrix_b, 16, 16, 16, __nv_bfloat16,
                           wmma::row_major> fBh[2], fBl[2];
#pragma unroll
            for (int nt = 0; nt < 2; ++nt) {
                wmma::load_matrix_sync(fBh[nt], Hh + nt * 16, 32);
                wmma::load_matrix_sync(fBl[nt], Hl + nt * 16, 32);
            }
#pragma unroll
            for (int mt = 0; mt < 2; ++mt)
#pragma unroll
                for (int nt = 0; nt < 2; ++nt) {
                    wmma::mma_sync(acc[mt][nt], fAh[tt][mt], fBh[nt], acc[mt][nt]);
                    wmma::mma_sync(acc[mt][nt], fAl[tt][mt], fBh[nt], acc[mt][nt]);
                    wmma::mma_sync(acc[mt][nt], fAh[tt][mt], fBl[nt], acc[mt][nt]);
                }
        }

        // store warp partials: zsh[w][j][b]
#pragma unroll
        for (int mt = 0; mt < 2; ++mt)
#pragma unroll
            for (int nt = 0; nt < 2; ++nt)
                wmma::store_matrix_sync(
                    zsh + (size_t)w * 1024 + mt * 512 + nt * 16,
                    acc[mt][nt], 32, wmma::mem_row_major);
        __syncthreads();

        // cell update: 256 units, one per thread
        const int nxt = cur ^ 1;
        {
            int u  = tid;
            int bu = u >> 3, jh = u & 7;
            float zq[4];
#pragma unroll
            for (int g = 0; g < 4; g++) {
                float s = xz[g];
                int off = (g * 8 + jh) * 32 + bu;
#pragma unroll
                for (int ww = 0; ww < 8; ww++)
                    s += zsh[ww * 1024 + off];
                zq[g] = s;
            }
            float cp = csh[u];
            float cn = sigf(zq[2] + 1.0f) * cp + sigf(zq[0]) * tanhf(zq[1]);
            float hn = sigf(zq[3]) * tanhf(cn);
            bool mask = (t < lensh[bu]);
            float hk = mask ? hn : hown[u];
            float ck = mask ? cn : cp;
            csh[u]  = ck;
            hown[u] = hk;
            int kg = blk * 8 + jh;
            out_h[((size_t)bu * TSTEP + t) * HS + kg] = mask ? hn : 0.0f;
            __nv_bfloat16 hhi = __float2bfloat16(hk);
            __nv_bfloat16 hlo = __float2bfloat16(hk - __bfloat162float(hhi));
            size_t hidx = (size_t)nxt * 32768 + (size_t)kg * 32 + bu;
            stg_cg_u16((unsigned short*)g_hbh + hidx, *(unsigned short*)&hhi);
            stg_cg_u16((unsigned short*)g_hbl + hidx, *(unsigned short*)&hlo);
            if (hc_final != nullptr && t == TSTEP - 1) {
                hc_final[(size_t)bu * HS + kg]         = hk;
                hc_final[32768 + (size_t)bu * HS + kg] = ck;
            }
        }

        bar_t += NBLK;
        grid_sync(bar_t);
        cur = nxt;
    }
}

// ---------------------------------------------------------------------------
extern "C" void kernel_launch(void* const* d_in, const int* in_sizes, int n_in,
                              void* d_out, int out_size)
{
    const float* x       = (const float*)d_in[0];
    const int*   lengths = (const int*)  d_in[1];
    const float* W0      = (const float*)d_in[2];
    const float* b0      = (const float*)d_in[3];
    const float* W1      = (const float*)d_in[4];
    const float* b1      = (const float*)d_in[5];
    float*       out     = (float*)d_out;

    (void)in_sizes; (void)n_in; (void)out_size;

    cudaFuncSetAttribute(rec_kernel,
                         cudaFuncAttributeMaxDynamicSharedMemorySize,
                         REC_SMEM_BYTES);
    cudaFuncSetAttribute(mm_kernel,
                         cudaFuncAttributeMaxDynamicSharedMemorySize,
                         MM_SMEM);

    float* xproj = nullptr;
    float* out0  = nullptr;
    __nv_bfloat16 *ah, *al, *wh, *wl;
    cudaGetSymbolAddress((void**)&xproj, g_xproj);
    cudaGetSymbolAddress((void**)&out0,  g_out0);
    cudaGetSymbolAddress((void**)&ah, g_ah);
    cudaGetSymbolAddress((void**)&al, g_al);
    cudaGetSymbolAddress((void**)&wh, g_wh);
    cudaGetSymbolAddress((void**)&wl, g_wl);

    dim3 mgrid(GSZ / 128, MROWS / 128);   // (32, 128)

    // Layer 0
    split_kernel<<<(MROWS * HS) / 1024, 256>>>(x, ah, al);
    split_kernel<<<(HS * GSZ) / 1024, 256>>>(W0, wh, wl);
    mm_kernel<<<mgrid, 256, MM_SMEM>>>(ah, al, wh, wl, b0, xproj);
    init_bar_kernel<<<1, 1>>>();
    rec_kernel<<<NBLK, 256, REC_SMEM_BYTES>>>(xproj, W0, lengths, out0, nullptr);

    // Layer 1
    split_kernel<<<(MROWS * HS) / 1024, 256>>>(out0, ah, al);
    split_kernel<<<(HS * GSZ) / 1024, 256>>>(W1, wh, wl);
    mm_kernel<<<mgrid, 256, MM_SMEM>>>(ah, al, wh, wl, b1, xproj);
    init_bar_kernel<<<1, 1>>>();
    rec_kernel<<<NBLK, 256, REC_SMEM_BYTES>>>(xproj, W1, lengths,
                                              out, out + (size_t)MROWS * HS);
}

// round 15
// speedup vs baseline: 1.8046x; 1.0491x over previous
#include <cuda_runtime.h>
#include <cuda_bf16.h>
#include <mma.h>
#include <cstdint>
#include <cstddef>

using namespace nvcuda;

// ---------------------------------------------------------------------------
// 2-layer TF LSTM: B=32, T=512, INSZ=HSZ=1024, G=4096.
// Output: concat(out1[32,512,1024], h1[32,1024], c1[32,1024]) f32.
// R15: rec — global grid barrier replaced by per-k-octant dataflow counters
//      (warp w waits only on its 16 producer CTAs, overlapped with staging).
//      Everything else = R14 (passing, 10.99ms).
// ---------------------------------------------------------------------------

#define BSZ   32
#define TSTEP 512
#define HS    1024
#define GSZ   4096
#define MROWS (BSZ * TSTEP)      // 16384
#define NBLK  128

typedef unsigned long long u64;

// ----------------------------- device scratch ------------------------------
__device__ __align__(16) float g_xproj[(size_t)MROWS * GSZ];
__device__ __align__(16) float g_out0 [(size_t)MROWS * HS];
__device__ __align__(16) __nv_bfloat16 g_hbh[2 * HS * BSZ];   // h hi, [buf][k][b]
__device__ __align__(16) __nv_bfloat16 g_hbl[2 * HS * BSZ];   // h lo
__device__ __align__(16) __nv_bfloat16 g_ah[(size_t)MROWS * HS];
__device__ __align__(16) __nv_bfloat16 g_al[(size_t)MROWS * HS];
__device__ __align__(16) __nv_bfloat16 g_wh[(size_t)HS * GSZ];
__device__ __align__(16) __nv_bfloat16 g_wl[(size_t)HS * GSZ];
__device__ unsigned g_cnt[8];    // per-k-octant producer counters

// ----------------------------- helpers -------------------------------------
__device__ __forceinline__ float sigf(float x) { return 1.0f / (1.0f + __expf(-x)); }

__device__ __forceinline__ void cpasync16(uint32_t s, const void* g) {
    asm volatile("cp.async.cg.shared.global [%0], [%1], 16;"
                 :: "r"(s), "l"(g) : "memory");
}
#define CP_COMMIT() asm volatile("cp.async.commit_group;" ::: "memory")
#define CP_WAIT(n)  asm volatile("cp.async.wait_group %0;" :: "n"(n) : "memory")

__device__ __forceinline__ void stg_cg_u16(unsigned short* p, unsigned short v) {
    asm volatile("st.global.cg.u16 [%0], %1;" :: "l"(p), "h"(v) : "memory");
}

__device__ __forceinline__ void arrive_cnt(unsigned* p) {
    asm volatile("red.release.gpu.global.add.u32 [%0], %1;"
                 :: "l"(p), "r"(1u) : "memory");
}
__device__ __forceinline__ void wait_cnt(const unsigned* p, unsigned target) {
    unsigned v;
    do {
        asm volatile("ld.acquire.gpu.global.u32 %0, [%1];"
                     : "=r"(v) : "l"(p) : "memory");
    } while (v < target);
}

__global__ void init_cnt_kernel() {
    if (threadIdx.x < 8) g_cnt[threadIdx.x] = 0u;
}

// ---------------------------------------------------------------------------
// split_kernel: fp32 -> bf16 hi/lo
// ---------------------------------------------------------------------------
__global__ void __launch_bounds__(256) split_kernel(
    const float* __restrict__ in, __nv_bfloat16* __restrict__ hi,
    __nv_bfloat16* __restrict__ lo)
{
    size_t i = ((size_t)blockIdx.x * 256 + threadIdx.x) * 4;
    float4 v = *(const float4*)(in + i);
    __nv_bfloat16 h0 = __float2bfloat16(v.x);
    __nv_bfloat16 h1 = __float2bfloat16(v.y);
    __nv_bfloat16 h2 = __float2bfloat16(v.z);
    __nv_bfloat16 h3 = __float2bfloat16(v.w);
    __nv_bfloat16 l0 = __float2bfloat16(v.x - __bfloat162float(h0));
    __nv_bfloat16 l1 = __float2bfloat16(v.y - __bfloat162float(h1));
    __nv_bfloat16 l2 = __float2bfloat16(v.z - __bfloat162float(h2));
    __nv_bfloat16 l3 = __float2bfloat16(v.w - __bfloat162float(h3));
    __nv_bfloat162* H = (__nv_bfloat162*)(hi + i);
    __nv_bfloat162* L = (__nv_bfloat162*)(lo + i);
    H[0] = __halves2bfloat162(h0, h1); H[1] = __halves2bfloat162(h2, h3);
    L[0] = __halves2bfloat162(l0, l1); L[1] = __halves2bfloat162(l2, l3);
}

// ---------------------------------------------------------------------------
// mm_kernel (R12, unchanged): C = Ah@Wh + Al@Wh + Ah@Wl + bias
// ---------------------------------------------------------------------------
#define LDA 40
#define LDB 136
#define AT_BYTES (128 * LDA * 2)
#define WT_BYTES (32 * LDB * 2)
#define STAGE    (2 * AT_BYTES + 2 * WT_BYTES)
#define MM_SMEM  (2 * STAGE)

__global__ void __launch_bounds__(256) mm_kernel(
    const __nv_bfloat16* __restrict__ Ah, const __nv_bfloat16* __restrict__ Al,
    const __nv_bfloat16* __restrict__ Bh, const __nv_bfloat16* __restrict__ Bl,
    const float* __restrict__ bias, float* __restrict__ C)
{
    extern __shared__ __align__(128) char smem[];
    __shared__ float biasS[128];

    const int tid = threadIdx.x;
    const int wid = tid >> 5;
    const int wm = wid >> 1, wn = wid & 1;
    const int m0 = blockIdx.y * 128;
    const int n0 = blockIdx.x * 128;

    if (tid < 128) biasS[tid] = bias[n0 + tid];

    uint32_t sbase;
    asm("{ .reg .u64 t; cvta.to.shared.u64 t, %1; cvt.u32.u64 %0, t; }"
        : "=r"(sbase) : "l"(smem));

    const int aR0 = (tid * 2)     >> 2, aC0 = ((tid * 2)     & 3) * 8;
    const int aR1 = (tid * 2 + 1) >> 2, aC1 = ((tid * 2 + 1) & 3) * 8;
    const int wR0 = (tid * 2)     >> 4, wC0 = ((tid * 2)     & 15) * 8;
    const int wR1 = (tid * 2 + 1) >> 4, wC1 = ((tid * 2 + 1) & 15) * 8;

    auto prefetch = [&](int k0, int s) {
        uint32_t st = sbase + s * STAGE;
        uint32_t sAh = st;
        uint32_t sAl = st + AT_BYTES;
        uint32_t sWh = st + 2 * AT_BYTES;
        uint32_t sWl = st + 2 * AT_BYTES + WT_BYTES;
        cpasync16(sAh + (aR0 * LDA + aC0) * 2, Ah + (size_t)(m0 + aR0) * HS + k0 + aC0);
        cpasync16(sAh + (aR1 * LDA + aC1) * 2, Ah + (size_t)(m0 + aR1) * HS + k0 + aC1);
        cpasync16(sAl + (aR0 * LDA + aC0) * 2, Al + (size_t)(m0 + aR0) * HS + k0 + aC0);
        cpasync16(sAl + (aR1 * LDA + aC1) * 2, Al + (size_t)(m0 + aR1) * HS + k0 + aC1);
        cpasync16(sWh + (wR0 * LDB + wC0) * 2, Bh + (size_t)(k0 + wR0) * GSZ + n0 + wC0);
        cpasync16(sWh + (wR1 * LDB + wC1) * 2, Bh + (size_t)(k0 + wR1) * GSZ + n0 + wC1);
        cpasync16(sWl + (wR0 * LDB + wC0) * 2, Bl + (size_t)(k0 + wR0) * GSZ + n0 + wC0);
        cpasync16(sWl + (wR1 * LDB + wC1) * 2, Bl + (size_t)(k0 + wR1) * GSZ + n0 + wC1);
        CP_COMMIT();
    };

    wmma::fragment<wmma::accumulator, 16, 16, 16, float> acc[2][4];
#pragma unroll
    for (int i = 0; i < 2; ++i)
#pragma unroll
        for (int j = 0; j < 4; ++j)
            wmma::fill_fragment(acc[i][j], 0.0f);

    prefetch(0, 0);

#pragma unroll 1
    for (int c = 0; c < 32; ++c) {
        if (c < 31) prefetch((c + 1) * 32, (c + 1) & 1);
        if (c < 31) { CP_WAIT(1); } else { CP_WAIT(0); }
        __syncthreads();

        const char* st = smem + (c & 1) * STAGE;
        const __nv_bfloat16* sAh = (const __nv_bfloat16*)st;
        const __nv_bfloat16* sAl = (const __nv_bfloat16*)(st + AT_BYTES);
        const __nv_bfloat16* sWh = (const __nv_bfloat16*)(st + 2 * AT_BYTES);
        const __nv_bfloat16* sWl = (const __nv_bfloat16*)(st + 2 * AT_BYTES + WT_BYTES);

#pragma unroll
        for (int ks = 0; ks < 2; ++ks) {
            wmma::fragment<wmma::matrix_a, 16, 16, 16, __nv_bfloat16,
                           wmma::row_major> ah[2], al[2];
            wmma::fragment<wmma::matrix_b, 16, 16, 16, __nv_bfloat16,
                           wmma::row_major> wh[4], wl[4];
#pragma unroll
            for (int i = 0; i < 2; ++i) {
                wmma::load_matrix_sync(ah[i],
                    sAh + (size_t)(wm * 32 + i * 16) * LDA + ks * 16, LDA);
                wmma::load_matrix_sync(al[i],
                    sAl + (size_t)(wm * 32 + i * 16) * LDA + ks * 16, LDA);
            }
#pragma unroll
            for (int j = 0; j < 4; ++j) {
                wmma::load_matrix_sync(wh[j],
                    sWh + (size_t)(ks * 16) * LDB + wn * 64 + j * 16, LDB);
                wmma::load_matrix_sync(wl[j],
                    sWl + (size_t)(ks * 16) * LDB + wn * 64 + j * 16, LDB);
            }
#pragma unroll
            for (int i = 0; i < 2; ++i)
#pragma unroll
                for (int j = 0; j < 4; ++j) {
                    wmma::mma_sync(acc[i][j], ah[i], wh[j], acc[i][j]);
                    wmma::mma_sync(acc[i][j], al[i], wh[j], acc[i][j]);
                    wmma::mma_sync(acc[i][j], ah[i], wl[j], acc[i][j]);
                }
        }
        __syncthreads();
    }

    float* Csh = (float*)smem;
#pragma unroll
    for (int i = 0; i < 2; ++i)
#pragma unroll
        for (int j = 0; j < 4; ++j)
            wmma::store_matrix_sync(
                Csh + (size_t)(wm * 32 + i * 16) * 128 + wn * 64 + j * 16,
                acc[i][j], 128, wmma::mem_row_major);
    __syncthreads();

#pragma unroll
    for (int r = 0; r < 16; ++r) {
        int f = tid + r * 256;
        int row = f >> 5, cc = (f & 31) * 4;
        float4 v = *(float4*)(Csh + (size_t)row * 128 + cc);
        v.x += biasS[cc + 0]; v.y += biasS[cc + 1];
        v.z += biasS[cc + 2]; v.w += biasS[cc + 3];
        *(float4*)(C + (size_t)(m0 + row) * GSZ + n0 + cc) = v;
    }
}

// ---------------------------------------------------------------------------
// Recurrence: persistent, 128 CTAs x 256 threads (8 warps).
// z^T[j][b] = Wh^T @ h, wmma bf16 3-term split; W A-frags in registers.
// Dataflow sync: warp w consumes k in [128w,128w+128) produced by CTAs
// [16w,16w+16) -> g_cnt[w] counters.  Warp w spins (lane 0, ld.acquire)
// until g_cnt[w] >= 16*(t+1), then stages its h via per-tile cp.async.
// End of step: arrive-only (red.release after a CTA-wide bar covering the
// cell-phase h stores).  2-buffer safety: a CTA overwrites h(t) only after
// all its warps observed h(t+1) complete => every CTA finished step t.
// ---------------------------------------------------------------------------
#define R_HST   0                        // 8 warps x 16384 B staging
#define R_ZSH   131072                   // 8 x [32j][32b] f32, 32768 B
#define R_CSH   163840                   // 256 f32
#define R_HOWN  164864                   // 256 f32
#define R_LEN   165888                   // 32 i32
#define REC_SMEM_BYTES 166016

__global__ void __launch_bounds__(256) rec_kernel(
    const float* __restrict__ xproj,
    const float* __restrict__ W,
    const int*   __restrict__ lengths,
    float*       __restrict__ out_h,
    float*       __restrict__ hc_final)
{
    extern __shared__ __align__(128) char sm[];
    float* zsh   = (float*)(sm + R_ZSH);
    float* csh   = (float*)(sm + R_CSH);
    float* hown  = (float*)(sm + R_HOWN);
    int*   lensh = (int*)(sm + R_LEN);

    const int tid  = threadIdx.x;
    const int blk  = blockIdx.x;
    const int w    = tid >> 5;
    const int lane = tid & 31;
    const int oct  = blk >> 4;           // this CTA's producer octant

    uint32_t sbase;
    asm("{ .reg .u64 t; cvta.to.shared.u64 t, %1; cvt.u32.u64 %0, t; }"
        : "=r"(sbase) : "l"(sm));

    // ---- preload W A-fragments into registers (col_major, ldm=32) ----
    wmma::fragment<wmma::matrix_a, 16, 16, 16, __nv_bfloat16,
                   wmma::col_major> fAh[8][2], fAl[8][2];
    {
        __nv_bfloat16* Wtmp = (__nv_bfloat16*)sm;   // 64KB scratch in staging
        for (int i = tid; i < 32768; i += 256) {
            int k = i >> 5, j = i & 31;
            int g = j >> 3, jh = j & 7;
            float v = W[(size_t)(HS + k) * GSZ + g * HS + blk * 8 + jh];
            Wtmp[i] = __float2bfloat16(v);
        }
        __syncthreads();
#pragma unroll
        for (int t = 0; t < 8; ++t)
#pragma unroll
            for (int mt = 0; mt < 2; ++mt)
                wmma::load_matrix_sync(fAh[t][mt],
                    Wtmp + (size_t)(w * 128 + t * 16) * 32 + mt * 16, 32);
        __syncthreads();
        for (int i = tid; i < 32768; i += 256) {
            int k = i >> 5, j = i & 31;
            int g = j >> 3, jh = j & 7;
            float v = W[(size_t)(HS + k) * GSZ + g * HS + blk * 8 + jh];
            __nv_bfloat16 hi = __float2bfloat16(v);
            Wtmp[i] = __float2bfloat16(v - __bfloat162float(hi));
        }
        __syncthreads();
#pragma unroll
        for (int t = 0; t < 8; ++t)
#pragma unroll
            for (int mt = 0; mt < 2; ++mt)
                wmma::load_matrix_sync(fAl[t][mt],
                    Wtmp + (size_t)(w * 128 + t * 16) * 32 + mt * 16, 32);
        __syncthreads();
    }

    if (tid < 32) lensh[tid] = lengths[tid];
    csh[tid] = 0.0f; hown[tid] = 0.0f;
    {   // zero h(0) bf16 slice (buffer 0)
        int k = blk * 8 + w, b = lane;
        stg_cg_u16((unsigned short*)g_hbh + (size_t)k * 32 + b, 0);
        stg_cg_u16((unsigned short*)g_hbl + (size_t)k * 32 + b, 0);
    }
    __syncthreads();
    if (tid == 0) arrive_cnt(&g_cnt[oct]);   // h(0) published

    int cur = 0;
    const uint32_t wst = sbase + R_HST + w * 16384;

    for (int t = 0; t < TSTEP; t++) {
        // hoisted xproj loads (consumed in cell phase)
        float xz[4];
        {
            int bu = tid >> 3, jh = tid & 7;
            const float* xp =
                xproj + ((size_t)(bu * TSTEP + t)) * GSZ + blk * 8 + jh;
#pragma unroll
            for (int g = 0; g < 4; g++) xz[g] = __ldcg(xp + g * HS);
        }

        // wait for this warp's 16 producer CTAs, then issue staging
        if (lane == 0) wait_cnt(&g_cnt[w], 16u * (unsigned)(t + 1));
        __syncwarp();

        const char* srcH = (const char*)(g_hbh + (size_t)cur * 32768 + (size_t)w * 128 * 32);
        const char* srcL = (const char*)(g_hbl + (size_t)cur * 32768 + (size_t)w * 128 * 32);
#pragma unroll
        for (int tt = 0; tt < 8; ++tt) {
            int o = lane * 32;   // 2x16B per lane
            cpasync16(wst + tt * 2048 + o,             srcH + tt * 1024 + o);
            cpasync16(wst + tt * 2048 + o + 16,        srcH + tt * 1024 + o + 16);
            cpasync16(wst + tt * 2048 + 1024 + o,      srcL + tt * 1024 + o);
            cpasync16(wst + tt * 2048 + 1024 + o + 16, srcL + tt * 1024 + o + 16);
            CP_COMMIT();
        }

        wmma::fragment<wmma::accumulator, 16, 16, 16, float> acc[2][2];
#pragma unroll
        for (int i = 0; i < 2; ++i)
#pragma unroll
            for (int j = 0; j < 2; ++j)
                wmma::fill_fragment(acc[i][j], 0.0f);

#pragma unroll
        for (int tt = 0; tt < 8; ++tt) {
            switch (tt) {
                case 0: CP_WAIT(7); break;
                case 1: CP_WAIT(6); break;
                case 2: CP_WAIT(5); break;
                case 3: CP_WAIT(4); break;
                case 4: CP_WAIT(3); break;
                case 5: CP_WAIT(2); break;
                case 6: CP_WAIT(1); break;
                default: CP_WAIT(0); break;
            }
            __syncwarp();

            const __nv_bfloat16* Hh =
                (const __nv_bfloat16*)(sm + R_HST + w * 16384 + tt * 2048);
            const __nv_bfloat16* Hl =
                (const __nv_bfloat16*)(sm + R_HST + w * 16384 + tt * 2048 + 1024);

            wmma::fragment<wmma::matrix_b, 16, 16, 16, __nv_bfloat16,
                           wmma::row_major> fBh[2], fBl[2];
#pragma unroll
            for (int nt = 0; nt < 2; ++nt) {
                wmma::load_matrix_sync(fBh[nt], Hh + nt * 16, 32);
                wmma::load_matrix_sync(fBl[nt], Hl + nt * 16, 32);
            }
#pragma unroll
            for (int mt = 0; mt < 2; ++mt)
#pragma unroll
                for (int nt = 0; nt < 2; ++nt) {
                    wmma::mma_sync(acc[mt][nt], fAh[tt][mt], fBh[nt], acc[mt][nt]);
                    wmma::mma_sync(acc[mt][nt], fAl[tt][mt], fBh[nt], acc[mt][nt]);
                    wmma::mma_sync(acc[mt][nt], fAh[tt][mt], fBl[nt], acc[mt][nt]);
                }
        }

        // store warp partials: zsh[w][j][b]
#pragma unroll
        for (int mt = 0; mt < 2; ++mt)
#pragma unroll
            for (int nt = 0; nt < 2; ++nt)
                wmma::store_matrix_sync(
                    zsh + (size_t)w * 1024 + mt * 512 + nt * 16,
                    acc[mt][nt], 32, wmma::mem_row_major);
        __syncthreads();   // all warps' waits passed + partials visible

        // cell update: 256 units, one per thread
        const int nxt = cur ^ 1;
        {
            int u  = tid;
            int bu = u >> 3, jh = u & 7;
            float zq[4];
#pragma unroll
            for (int g = 0; g < 4; g++) {
                float s = xz[g];
                int off = (g * 8 + jh) * 32 + bu;
#pragma unroll
                for (int ww = 0; ww < 8; ww++)
                    s += zsh[ww * 1024 + off];
                zq[g] = s;
            }
            float cp = csh[u];
            float cn = sigf(zq[2] + 1.0f) * cp + sigf(zq[0]) * tanhf(zq[1]);
            float hn = sigf(zq[3]) * tanhf(cn);
            bool mask = (t < lensh[bu]);
            float hk = mask ? hn : hown[u];
            float ck = mask ? cn : cp;
            csh[u]  = ck;
            hown[u] = hk;
            int kg = blk * 8 + jh;
            out_h[((size_t)bu * TSTEP + t) * HS + kg] = mask ? hn : 0.0f;
            __nv_bfloat16 hhi = __float2bfloat16(hk);
            __nv_bfloat16 hlo = __float2bfloat16(hk - __bfloat162float(hhi));
            size_t hidx = (size_t)nxt * 32768 + (size_t)kg * 32 + bu;
            stg_cg_u16((unsigned short*)g_hbh + hidx, *(unsigned short*)&hhi);
            stg_cg_u16((unsigned short*)g_hbl + hidx, *(unsigned short*)&hlo);
            if (hc_final != nullptr && t == TSTEP - 1) {
                hc_final[(size_t)bu * HS + kg]         = hk;
                hc_final[32768 + (size_t)bu * HS + kg] = ck;
            }
        }

        // publish h(t+1): arrive-only (release covers the h stores above)
        __syncthreads();
        if (tid == 0) arrive_cnt(&g_cnt[oct]);
        cur = nxt;
    }
}

// ---------------------------------------------------------------------------
extern "C" void kernel_launch(void* const* d_in, const int* in_sizes, int n_in,
                              void* d_out, int out_size)
{
    const float* x       = (const float*)d_in[0];
    const int*   lengths = (const int*)  d_in[1];
    const float* W0      = (const float*)d_in[2];
    const float* b0      = (const float*)d_in[3];
    const float* W1      = (const float*)d_in[4];
    const float* b1      = (const float*)d_in[5];
    float*       out     = (float*)d_out;

    (void)in_sizes; (void)n_in; (void)out_size;

    cudaFuncSetAttribute(rec_kernel,
                         cudaFuncAttributeMaxDynamicSharedMemorySize,
                         REC_SMEM_BYTES);
    cudaFuncSetAttribute(mm_kernel,
                         cudaFuncAttributeMaxDynamicSharedMemorySize,
                         MM_SMEM);

    float* xproj = nullptr;
    float* out0  = nullptr;
    __nv_bfloat16 *ah, *al, *wh, *wl;
    cudaGetSymbolAddress((void**)&xproj, g_xproj);
    cudaGetSymbolAddress((void**)&out0,  g_out0);
    cudaGetSymbolAddress((void**)&ah, g_ah);
    cudaGetSymbolAddress((void**)&al, g_al);
    cudaGetSymbolAddress((void**)&wh, g_wh);
    cudaGetSymbolAddress((void**)&wl, g_wl);

    dim3 mgrid(GSZ / 128, MROWS / 128);   // (32, 128)

    // Layer 0
    split_kernel<<<(MROWS * HS) / 1024, 256>>>(x, ah, al);
    split_kernel<<<(HS * GSZ) / 1024, 256>>>(W0, wh, wl);
    mm_kernel<<<mgrid, 256, MM_SMEM>>>(ah, al, wh, wl, b0, xproj);
    init_cnt_kernel<<<1, 32>>>();
    rec_kernel<<<NBLK, 256, REC_SMEM_BYTES>>>(xproj, W0, lengths, out0, nullptr);

    // Layer 1
    split_kernel<<<(MROWS * HS) / 1024, 256>>>(out0, ah, al);
    split_kernel<<<(HS * GSZ) / 1024, 256>>>(W1, wh, wl);
    mm_kernel<<<mgrid, 256, MM_SMEM>>>(ah, al, wh, wl, b1, xproj);
    init_cnt_kernel<<<1, 32>>>();
    rec_kernel<<<NBLK, 256, REC_SMEM_BYTES>>>(xproj, W1, lengths,
                                              out, out + (size_t)MROWS * HS);
}